// round 1
// baseline (speedup 1.0000x reference)
#include <cuda_runtime.h>
#include <math.h>

#define EMBED 1024
#define NHEAD 16
#define HDIM  64
#define BATCH 2
#define QLEN  2048
#define KLEN  2048
#define MROWS (BATCH*QLEN)   // 4096
#define ATT_PAD 68           // 64 + 4 pad: conflict-free smem rows

// Scratch (allocation-free: static device globals)
__device__ float g_Qp[(size_t)MROWS * EMBED];
__device__ float g_Kp[(size_t)MROWS * EMBED];
__device__ float g_Vp[(size_t)MROWS * EMBED];
__device__ float g_ctx[(size_t)MROWS * EMBED];

// ---------------------------------------------------------------------------
// C[m,n] = scale * sum_k A[m,k] * W[n,k]
// A: [M,K] row-major, W: [N,K] row-major (i.e. C = A @ W^T)
// 128x128 block tile, BK=8, 256 threads, 8x8 register micro-tile (2x2 float4).
// M,N,K assumed multiples of 128 (true here: 4096/1024/1024).
// ---------------------------------------------------------------------------
__global__ __launch_bounds__(256) void gemm_atw(const float* __restrict__ A,
                                                const float* __restrict__ W,
                                                float* __restrict__ C,
                                                int M, int N, int K, float scale)
{
    __shared__ float As[8][128];
    __shared__ float Bs[8][128];
    const int tid = threadIdx.x;
    const int tx  = tid & 15;
    const int ty  = tid >> 4;
    const int m0  = blockIdx.y * 128;
    const int n0  = blockIdx.x * 128;
    const int lrow = tid >> 1;          // 0..127
    const int lk   = (tid & 1) * 4;     // 0 or 4
    const float* Ap = A + (size_t)(m0 + lrow) * K + lk;
    const float* Wp = W + (size_t)(n0 + lrow) * K + lk;

    float acc[8][8];
#pragma unroll
    for (int i = 0; i < 8; i++)
#pragma unroll
        for (int j = 0; j < 8; j++) acc[i][j] = 0.f;

    for (int k0 = 0; k0 < K; k0 += 8) {
        float4 av = *(const float4*)(Ap + k0);
        float4 wv = *(const float4*)(Wp + k0);
        As[lk + 0][lrow] = av.x; As[lk + 1][lrow] = av.y;
        As[lk + 2][lrow] = av.z; As[lk + 3][lrow] = av.w;
        Bs[lk + 0][lrow] = wv.x; Bs[lk + 1][lrow] = wv.y;
        Bs[lk + 2][lrow] = wv.z; Bs[lk + 3][lrow] = wv.w;
        __syncthreads();
#pragma unroll
        for (int kk = 0; kk < 8; kk++) {
            float a[8], b[8];
#pragma unroll
            for (int i = 0; i < 4; i++) {
                a[i]     = As[kk][ty * 4 + i];
                a[i + 4] = As[kk][64 + ty * 4 + i];
                b[i]     = Bs[kk][tx * 4 + i];
                b[i + 4] = Bs[kk][64 + tx * 4 + i];
            }
#pragma unroll
            for (int i = 0; i < 8; i++)
#pragma unroll
                for (int j = 0; j < 8; j++)
                    acc[i][j] += a[i] * b[j];
        }
        __syncthreads();
    }

#pragma unroll
    for (int i = 0; i < 8; i++) {
        int r = m0 + ((i < 4) ? (ty * 4 + i) : (64 + ty * 4 + (i - 4)));
        float4 v0, v1;
        v0.x = acc[i][0] * scale; v0.y = acc[i][1] * scale;
        v0.z = acc[i][2] * scale; v0.w = acc[i][3] * scale;
        v1.x = acc[i][4] * scale; v1.y = acc[i][5] * scale;
        v1.z = acc[i][6] * scale; v1.w = acc[i][7] * scale;
        *(float4*)(C + (size_t)r * N + n0 + tx * 4)       = v0;
        *(float4*)(C + (size_t)r * N + n0 + 64 + tx * 4)  = v1;
    }
}

// ---------------------------------------------------------------------------
// Flash attention over projected tensors.
// Grid: (QLEN/64, NHEAD, BATCH). 256 threads.
// Each block: 64 query rows for one (b,h). Online softmax over KLEN in tiles
// of 64 keys. Thread mapping: r = tid/4 (query row), q4 = tid%4:
//   - S phase: thread computes s for keys c = j*4+q4 (16 keys)
//   - PV phase: exchanges p across the 4 row-threads via shfl_xor, accumulates
//     its d-slice d0 = q4*16 .. +16 over all 64 keys.
// Scale 1/sqrt(EMBED) is pre-folded into g_Qp. Mask penalty = mask*1e4.
// ---------------------------------------------------------------------------
__global__ __launch_bounds__(256) void attn_kernel(const int* __restrict__ mask)
{
    extern __shared__ float sm[];
    float* Qs  = sm;                       // 64 x ATT_PAD
    float* Ks  = sm + 64 * ATT_PAD;        // 64 x ATT_PAD
    float* Vs  = sm + 2 * 64 * ATT_PAD;    // 64 x ATT_PAD
    float* pen = sm + 3 * 64 * ATT_PAD;    // 64

    const int tid = threadIdx.x;
    const int qt = blockIdx.x, h = blockIdx.y, b = blockIdx.z;
    const int q0 = qt * 64;

    // Load Q tile [64 rows x 64 dims]
    const float* Qbase = g_Qp + (size_t)(b * QLEN + q0) * EMBED + h * HDIM;
#pragma unroll
    for (int j = 0; j < 4; j++) {
        int e = (tid + j * 256) * 4;    // 0..4092 step 4
        int row = e >> 6, col = e & 63;
        *(float4*)&Qs[row * ATT_PAD + col] =
            *(const float4*)(Qbase + (size_t)row * EMBED + col);
    }

    const int r  = tid >> 2;
    const int q4 = tid & 3;
    const int d0 = q4 * 16;

    float m_prev = -INFINITY, l = 0.f;
    float acc[16];
#pragma unroll
    for (int dd = 0; dd < 16; dd++) acc[dd] = 0.f;

    for (int kt = 0; kt < KLEN / 64; kt++) {
        const int k0 = kt * 64;
        __syncthreads();   // protect previous iteration's reads of Ks/Vs
        const float* Kbase = g_Kp + (size_t)(b * KLEN + k0) * EMBED + h * HDIM;
        const float* Vbase = g_Vp + (size_t)(b * KLEN + k0) * EMBED + h * HDIM;
#pragma unroll
        for (int j = 0; j < 4; j++) {
            int e = (tid + j * 256) * 4;
            int row = e >> 6, col = e & 63;
            *(float4*)&Ks[row * ATT_PAD + col] =
                *(const float4*)(Kbase + (size_t)row * EMBED + col);
            *(float4*)&Vs[row * ATT_PAD + col] =
                *(const float4*)(Vbase + (size_t)row * EMBED + col);
        }
        if (tid < 64)
            pen[tid] = mask[b * KLEN + k0 + tid] ? 10000.0f : 0.0f;
        __syncthreads();

        // S = Q . K^T for 16 keys (c = j*4 + q4)
        float s[16];
#pragma unroll
        for (int j = 0; j < 16; j++) s[j] = 0.f;
#pragma unroll
        for (int d4 = 0; d4 < 64; d4 += 4) {
            float4 qv = *(float4*)&Qs[r * ATT_PAD + d4];
#pragma unroll
            for (int j = 0; j < 16; j++) {
                float4 kv = *(float4*)&Ks[(j * 4 + q4) * ATT_PAD + d4];
                s[j] += qv.x * kv.x + qv.y * kv.y + qv.z * kv.z + qv.w * kv.w;
            }
        }

        float mx = -INFINITY;
#pragma unroll
        for (int j = 0; j < 16; j++) {
            s[j] -= pen[j * 4 + q4];
            mx = fmaxf(mx, s[j]);
        }
        mx = fmaxf(mx, __shfl_xor_sync(0xFFFFFFFFu, mx, 1));
        mx = fmaxf(mx, __shfl_xor_sync(0xFFFFFFFFu, mx, 2));

        const float m_new = fmaxf(m_prev, mx);
        const float alpha = __expf(m_prev - m_new);

        float p[16];
        float lt = 0.f;
#pragma unroll
        for (int j = 0; j < 16; j++) {
            p[j] = __expf(s[j] - m_new);
            lt += p[j];
        }
        lt += __shfl_xor_sync(0xFFFFFFFFu, lt, 1);
        lt += __shfl_xor_sync(0xFFFFFFFFu, lt, 2);
        l = l * alpha + lt;
#pragma unroll
        for (int dd = 0; dd < 16; dd++) acc[dd] *= alpha;
        m_prev = m_new;

        // PV: all 64 keys, this thread's 16-wide d-slice
#pragma unroll
        for (int mm = 0; mm < 4; mm++) {
            const int cq = q4 ^ mm;
#pragma unroll
            for (int j = 0; j < 16; j++) {
                float pv = __shfl_xor_sync(0xFFFFFFFFu, p[j], mm);
                const float* vrow = &Vs[(j * 4 + cq) * ATT_PAD + d0];
#pragma unroll
                for (int dd = 0; dd < 16; dd += 4) {
                    float4 vv = *(float4*)(vrow + dd);
                    acc[dd + 0] += pv * vv.x;
                    acc[dd + 1] += pv * vv.y;
                    acc[dd + 2] += pv * vv.z;
                    acc[dd + 3] += pv * vv.w;
                }
            }
        }
    }

    const float inv = 1.0f / l;
    float* obase = g_ctx + (size_t)(b * QLEN + q0 + r) * EMBED + h * HDIM + d0;
#pragma unroll
    for (int dd = 0; dd < 16; dd += 4) {
        float4 o;
        o.x = acc[dd + 0] * inv; o.y = acc[dd + 1] * inv;
        o.z = acc[dd + 2] * inv; o.w = acc[dd + 3] * inv;
        *(float4*)(obase + dd) = o;
    }
}

// ---------------------------------------------------------------------------
extern "C" void kernel_launch(void* const* d_in, const int* in_sizes, int n_in,
                              void* d_out, int out_size)
{
    (void)in_sizes; (void)n_in; (void)out_size;
    const float* query = (const float*)d_in[0];
    const float* key   = (const float*)d_in[1];
    const float* val   = (const float*)d_in[2];
    const int*   mask  = (const int*)  d_in[3];
    const float* Wq    = (const float*)d_in[4];
    const float* Wk    = (const float*)d_in[5];
    const float* Wv    = (const float*)d_in[6];
    const float* Wo    = (const float*)d_in[7];
    float* out = (float*)d_out;

    float *pQ, *pK, *pV, *pC;
    cudaGetSymbolAddress((void**)&pQ, g_Qp);
    cudaGetSymbolAddress((void**)&pK, g_Kp);
    cudaGetSymbolAddress((void**)&pV, g_Vp);
    cudaGetSymbolAddress((void**)&pC, g_ctx);

    const int attn_smem = (3 * 64 * ATT_PAD + 64) * (int)sizeof(float); // 52480
    cudaFuncSetAttribute(attn_kernel,
                         cudaFuncAttributeMaxDynamicSharedMemorySize, attn_smem);

    dim3 gGemm(EMBED / 128, MROWS / 128);   // (8, 32)
    const float inv_sqrt_e = 1.0f / 32.0f;  // 1/sqrt(1024), folded into Qp

    gemm_atw<<<gGemm, 256>>>(query, Wq, pQ, MROWS, EMBED, EMBED, inv_sqrt_e);
    gemm_atw<<<gGemm, 256>>>(key,   Wk, pK, MROWS, EMBED, EMBED, 1.0f);
    gemm_atw<<<gGemm, 256>>>(val,   Wv, pV, MROWS, EMBED, EMBED, 1.0f);

    dim3 gAttn(QLEN / 64, NHEAD, BATCH);    // (32, 16, 2)
    attn_kernel<<<gAttn, 256, attn_smem>>>(mask);

    gemm_atw<<<gGemm, 256>>>(pC, Wo, out, MROWS, EMBED, EMBED, 1.0f);
}

// round 2
// speedup vs baseline: 1.0470x; 1.0470x over previous
#include <cuda_runtime.h>
#include <math.h>
#include <stdint.h>

#define EMBED 1024
#define NHEAD 16
#define HDIM  64
#define BATCH 2
#define QLEN  2048
#define KLEN  2048
#define MROWS (BATCH*QLEN)   // 4096
#define ATT_PAD 68           // 64 + 4 pad: conflict-free smem rows
#define SK 36                // smem k-stride (32 + 4 pad): conflict-free frags

// Scratch (allocation-free: static device globals)
__device__ float g_Qp[(size_t)MROWS * EMBED];
__device__ float g_Kp[(size_t)MROWS * EMBED];
__device__ float g_Vp[(size_t)MROWS * EMBED];
__device__ float g_ctx[(size_t)MROWS * EMBED];

// ---------------------------------------------------------------------------
// tf32 helpers
// ---------------------------------------------------------------------------
__device__ __forceinline__ uint32_t f2tf(float x) {
    uint32_t r;
    asm("cvt.rna.tf32.f32 %0, %1;" : "=r"(r) : "f"(x));
    return r;
}

__device__ __forceinline__ void mma8(float* c, const uint32_t* a, const uint32_t* b) {
    asm volatile(
        "mma.sync.aligned.m16n8k8.row.col.f32.tf32.tf32.f32 "
        "{%0,%1,%2,%3}, {%4,%5,%6,%7}, {%8,%9}, {%0,%1,%2,%3};\n"
        : "+f"(c[0]), "+f"(c[1]), "+f"(c[2]), "+f"(c[3])
        : "r"(a[0]), "r"(a[1]), "r"(a[2]), "r"(a[3]), "r"(b[0]), "r"(b[1]));
}

// ---------------------------------------------------------------------------
// C[m,n] = scale * sum_k A[m,k] * W[n,k]   (C = A @ W^T), 3xTF32 tensor-core.
// A: [M,K] row-major, W: [N,K] row-major. M,N,K multiples of 128.
// Block: 128x128 tile, BK=32, 256 threads = 8 warps (4 m x 2 n),
// warp tile 32x64 = 2 m16-tiles x 8 n8-tiles, mma.m16n8k8 tf32.
// Split-precision: x = big(tf32) + res; D += Ab*Bb + Ar*Bb + Ab*Br.
// ---------------------------------------------------------------------------
__global__ __launch_bounds__(256) void gemm_tc(const float* __restrict__ A,
                                               const float* __restrict__ W,
                                               float* __restrict__ C,
                                               int M, int N, int K, float scale)
{
    __shared__ float As[128 * SK];
    __shared__ float Bs[128 * SK];
    const int tid  = threadIdx.x;
    const int lane = tid & 31;
    const int w    = tid >> 5;
    const int g    = lane >> 2;     // 0..7
    const int tk   = lane & 3;      // 0..3
    const int wm   = (w & 3) * 32;  // warp m base in tile
    const int wn   = (w >> 2) * 64; // warp n base in tile
    const int m0   = blockIdx.y * 128;
    const int n0   = blockIdx.x * 128;

    float acc[2][8][4];
#pragma unroll
    for (int mt = 0; mt < 2; mt++)
#pragma unroll
        for (int nt = 0; nt < 8; nt++)
#pragma unroll
            for (int r = 0; r < 4; r++) acc[mt][nt][r] = 0.f;

    for (int k0 = 0; k0 < K; k0 += 32) {
#pragma unroll
        for (int i = 0; i < 4; i++) {
            int l   = tid + i * 256;       // 0..1023
            int row = l >> 3;              // 0..127
            int kq  = (l & 7) * 4;         // 0..28
            *(float4*)&As[row * SK + kq] =
                *(const float4*)(A + (size_t)(m0 + row) * K + k0 + kq);
            *(float4*)&Bs[row * SK + kq] =
                *(const float4*)(W + (size_t)(n0 + row) * K + k0 + kq);
        }
        __syncthreads();

#pragma unroll
        for (int kk = 0; kk < 32; kk += 8) {
            uint32_t ab[2][4], ar[2][4];
#pragma unroll
            for (int mt = 0; mt < 2; mt++) {
#pragma unroll
                for (int r = 0; r < 4; r++) {
                    int mrow = wm + mt * 16 + g + ((r & 1) ? 8 : 0);
                    int kcol = kk + tk + ((r & 2) ? 4 : 0);
                    float x = As[mrow * SK + kcol];
                    uint32_t b = f2tf(x);
                    ab[mt][r] = b;
                    ar[mt][r] = f2tf(x - __uint_as_float(b));
                }
            }
            uint32_t bb[8][2], br[8][2];
#pragma unroll
            for (int nt = 0; nt < 8; nt++) {
#pragma unroll
                for (int r = 0; r < 2; r++) {
                    int nrow = wn + nt * 8 + g;
                    int kcol = kk + tk + r * 4;
                    float x = Bs[nrow * SK + kcol];
                    uint32_t b = f2tf(x);
                    bb[nt][r] = b;
                    br[nt][r] = f2tf(x - __uint_as_float(b));
                }
            }
#pragma unroll
            for (int mt = 0; mt < 2; mt++)
#pragma unroll
                for (int nt = 0; nt < 8; nt++) {
                    mma8(acc[mt][nt], ab[mt], bb[nt]);
                    mma8(acc[mt][nt], ar[mt], bb[nt]);
                    mma8(acc[mt][nt], ab[mt], br[nt]);
                }
        }
        __syncthreads();
    }

    // Epilogue: c0,c1 -> (row=g, col=2tk,2tk+1); c2,c3 -> row=g+8
#pragma unroll
    for (int mt = 0; mt < 2; mt++) {
#pragma unroll
        for (int nt = 0; nt < 8; nt++) {
            int m = m0 + wm + mt * 16 + g;
            int n = n0 + wn + nt * 8 + 2 * tk;
            float2 v0, v1;
            v0.x = acc[mt][nt][0] * scale; v0.y = acc[mt][nt][1] * scale;
            v1.x = acc[mt][nt][2] * scale; v1.y = acc[mt][nt][3] * scale;
            *(float2*)(C + (size_t)m * N + n) = v0;
            *(float2*)(C + (size_t)(m + 8) * N + n) = v1;
        }
    }
}

// ---------------------------------------------------------------------------
// Flash attention over projected tensors (unchanged from R1; fp32 SIMT).
// Grid: (QLEN/64, NHEAD, BATCH). 256 threads.
// ---------------------------------------------------------------------------
__global__ __launch_bounds__(256) void attn_kernel(const int* __restrict__ mask)
{
    extern __shared__ float sm[];
    float* Qs  = sm;                       // 64 x ATT_PAD
    float* Ks  = sm + 64 * ATT_PAD;        // 64 x ATT_PAD
    float* Vs  = sm + 2 * 64 * ATT_PAD;    // 64 x ATT_PAD
    float* pen = sm + 3 * 64 * ATT_PAD;    // 64

    const int tid = threadIdx.x;
    const int qt = blockIdx.x, h = blockIdx.y, b = blockIdx.z;
    const int q0 = qt * 64;

    const float* Qbase = g_Qp + (size_t)(b * QLEN + q0) * EMBED + h * HDIM;
#pragma unroll
    for (int j = 0; j < 4; j++) {
        int e = (tid + j * 256) * 4;
        int row = e >> 6, col = e & 63;
        *(float4*)&Qs[row * ATT_PAD + col] =
            *(const float4*)(Qbase + (size_t)row * EMBED + col);
    }

    const int r  = tid >> 2;
    const int q4 = tid & 3;
    const int d0 = q4 * 16;

    float m_prev = -INFINITY, l = 0.f;
    float acc[16];
#pragma unroll
    for (int dd = 0; dd < 16; dd++) acc[dd] = 0.f;

    for (int kt = 0; kt < KLEN / 64; kt++) {
        const int k0 = kt * 64;
        __syncthreads();
        const float* Kbase = g_Kp + (size_t)(b * KLEN + k0) * EMBED + h * HDIM;
        const float* Vbase = g_Vp + (size_t)(b * KLEN + k0) * EMBED + h * HDIM;
#pragma unroll
        for (int j = 0; j < 4; j++) {
            int e = (tid + j * 256) * 4;
            int row = e >> 6, col = e & 63;
            *(float4*)&Ks[row * ATT_PAD + col] =
                *(const float4*)(Kbase + (size_t)row * EMBED + col);
            *(float4*)&Vs[row * ATT_PAD + col] =
                *(const float4*)(Vbase + (size_t)row * EMBED + col);
        }
        if (tid < 64)
            pen[tid] = mask[b * KLEN + k0 + tid] ? 10000.0f : 0.0f;
        __syncthreads();

        float s[16];
#pragma unroll
        for (int j = 0; j < 16; j++) s[j] = 0.f;
#pragma unroll
        for (int d4 = 0; d4 < 64; d4 += 4) {
            float4 qv = *(float4*)&Qs[r * ATT_PAD + d4];
#pragma unroll
            for (int j = 0; j < 16; j++) {
                float4 kv = *(float4*)&Ks[(j * 4 + q4) * ATT_PAD + d4];
                s[j] += qv.x * kv.x + qv.y * kv.y + qv.z * kv.z + qv.w * kv.w;
            }
        }

        float mx = -INFINITY;
#pragma unroll
        for (int j = 0; j < 16; j++) {
            s[j] -= pen[j * 4 + q4];
            mx = fmaxf(mx, s[j]);
        }
        mx = fmaxf(mx, __shfl_xor_sync(0xFFFFFFFFu, mx, 1));
        mx = fmaxf(mx, __shfl_xor_sync(0xFFFFFFFFu, mx, 2));

        const float m_new = fmaxf(m_prev, mx);
        const float alpha = __expf(m_prev - m_new);

        float p[16];
        float lt = 0.f;
#pragma unroll
        for (int j = 0; j < 16; j++) {
            p[j] = __expf(s[j] - m_new);
            lt += p[j];
        }
        lt += __shfl_xor_sync(0xFFFFFFFFu, lt, 1);
        lt += __shfl_xor_sync(0xFFFFFFFFu, lt, 2);
        l = l * alpha + lt;
#pragma unroll
        for (int dd = 0; dd < 16; dd++) acc[dd] *= alpha;
        m_prev = m_new;

#pragma unroll
        for (int mm = 0; mm < 4; mm++) {
            const int cq = q4 ^ mm;
#pragma unroll
            for (int j = 0; j < 16; j++) {
                float pv = __shfl_xor_sync(0xFFFFFFFFu, p[j], mm);
                const float* vrow = &Vs[(j * 4 + cq) * ATT_PAD + d0];
#pragma unroll
                for (int dd = 0; dd < 16; dd += 4) {
                    float4 vv = *(float4*)(vrow + dd);
                    acc[dd + 0] += pv * vv.x;
                    acc[dd + 1] += pv * vv.y;
                    acc[dd + 2] += pv * vv.z;
                    acc[dd + 3] += pv * vv.w;
                }
            }
        }
    }

    const float inv = 1.0f / l;
    float* obase = g_ctx + (size_t)(b * QLEN + q0 + r) * EMBED + h * HDIM + d0;
#pragma unroll
    for (int dd = 0; dd < 16; dd += 4) {
        float4 o;
        o.x = acc[dd + 0] * inv; o.y = acc[dd + 1] * inv;
        o.z = acc[dd + 2] * inv; o.w = acc[dd + 3] * inv;
        *(float4*)(obase + dd) = o;
    }
}

// ---------------------------------------------------------------------------
extern "C" void kernel_launch(void* const* d_in, const int* in_sizes, int n_in,
                              void* d_out, int out_size)
{
    (void)in_sizes; (void)n_in; (void)out_size;
    const float* query = (const float*)d_in[0];
    const float* key   = (const float*)d_in[1];
    const float* val   = (const float*)d_in[2];
    const int*   mask  = (const int*)  d_in[3];
    const float* Wq    = (const float*)d_in[4];
    const float* Wk    = (const float*)d_in[5];
    const float* Wv    = (const float*)d_in[6];
    const float* Wo    = (const float*)d_in[7];
    float* out = (float*)d_out;

    float *pQ, *pK, *pV, *pC;
    cudaGetSymbolAddress((void**)&pQ, g_Qp);
    cudaGetSymbolAddress((void**)&pK, g_Kp);
    cudaGetSymbolAddress((void**)&pV, g_Vp);
    cudaGetSymbolAddress((void**)&pC, g_ctx);

    const int attn_smem = (3 * 64 * ATT_PAD + 64) * (int)sizeof(float); // 52480
    cudaFuncSetAttribute(attn_kernel,
                         cudaFuncAttributeMaxDynamicSharedMemorySize, attn_smem);

    dim3 gGemm(EMBED / 128, MROWS / 128);   // (8, 32)
    const float inv_sqrt_e = 1.0f / 32.0f;  // 1/sqrt(1024), folded into Qp

    gemm_tc<<<gGemm, 256>>>(query, Wq, pQ, MROWS, EMBED, EMBED, inv_sqrt_e);
    gemm_tc<<<gGemm, 256>>>(key,   Wk, pK, MROWS, EMBED, EMBED, 1.0f);
    gemm_tc<<<gGemm, 256>>>(val,   Wv, pV, MROWS, EMBED, EMBED, 1.0f);

    dim3 gAttn(QLEN / 64, NHEAD, BATCH);    // (32, 16, 2)
    attn_kernel<<<gAttn, 256, attn_smem>>>(mask);

    gemm_tc<<<gGemm, 256>>>(pC, Wo, out, MROWS, EMBED, EMBED, 1.0f);
}

// round 3
// speedup vs baseline: 1.6004x; 1.5286x over previous
#include <cuda_runtime.h>
#include <math.h>
#include <stdint.h>

#define EMBED 1024
#define NHEAD 16
#define HDIM  64
#define BATCH 2
#define QLEN  2048
#define KLEN  2048
#define MROWS (BATCH*QLEN)   // 4096

// Scratch (allocation-free: static device globals)
__device__ float g_Qp[(size_t)MROWS * EMBED];
__device__ float g_Kp[(size_t)MROWS * EMBED];
__device__ float g_Vp[(size_t)MROWS * EMBED];
__device__ float g_ctx[(size_t)MROWS * EMBED];

// ---------------------------------------------------------------------------
// tf32 helpers
// ---------------------------------------------------------------------------
__device__ __forceinline__ uint32_t f2tf(float x) {
    uint32_t r;
    asm("cvt.rna.tf32.f32 %0, %1;" : "=r"(r) : "f"(x));
    return r;
}

// split x into tf32 big + tf32 residual, both returned as float bit patterns
__device__ __forceinline__ float2 split2(float x) {
    uint32_t b = f2tf(x);
    float fb = __uint_as_float(b);
    uint32_t r = f2tf(x - fb);
    return make_float2(fb, __uint_as_float(r));
}

__device__ __forceinline__ void mma8(float* c, const uint32_t* a, const uint32_t* b) {
    asm volatile(
        "mma.sync.aligned.m16n8k8.row.col.f32.tf32.tf32.f32 "
        "{%0,%1,%2,%3}, {%4,%5,%6,%7}, {%8,%9}, {%0,%1,%2,%3};\n"
        : "+f"(c[0]), "+f"(c[1]), "+f"(c[2]), "+f"(c[3])
        : "r"(a[0]), "r"(a[1]), "r"(a[2]), "r"(a[3]), "r"(b[0]), "r"(b[1]));
}

// ---------------------------------------------------------------------------
// GEMM: C[m,n] = scale * sum_k A[m,k]*W[n,k]  (C = A @ W^T), 3xTF32.
// Split precomputed at smem store: layout pos = row*GKS + k*2 + {0=big,1=res},
// GKS=72 -> LDS.64 fragment reads are bank-conflict-free.
// Block 128x128, BK=32, 256 thr = 8 warps (4m x 2n), warp 32x64.
// ---------------------------------------------------------------------------
#define GKS 72
#define GEMM_SMEM (2 * 128 * GKS * 4)   // 73728 B

__global__ __launch_bounds__(256) void gemm_tc(const float* __restrict__ A,
                                               const float* __restrict__ W,
                                               float* __restrict__ C,
                                               int M, int N, int K, float scale)
{
    extern __shared__ float smg[];
    float* As = smg;
    float* Bs = smg + 128 * GKS;
    const int tid  = threadIdx.x;
    const int lane = tid & 31;
    const int w    = tid >> 5;
    const int g    = lane >> 2;
    const int tk   = lane & 3;
    const int wm   = (w & 3) * 32;
    const int wn   = (w >> 2) * 64;
    const int m0   = blockIdx.y * 128;
    const int n0   = blockIdx.x * 128;

    float acc[2][8][4];
#pragma unroll
    for (int mt = 0; mt < 2; mt++)
#pragma unroll
        for (int nt = 0; nt < 8; nt++)
#pragma unroll
            for (int r = 0; r < 4; r++) acc[mt][nt][r] = 0.f;

    for (int k0 = 0; k0 < K; k0 += 32) {
#pragma unroll
        for (int i = 0; i < 4; i++) {
            int l   = tid + i * 256;
            int row = l >> 3;
            int kq  = (l & 7) * 4;
            float4 a = *(const float4*)(A + (size_t)(m0 + row) * K + k0 + kq);
            float4 b = *(const float4*)(W + (size_t)(n0 + row) * K + k0 + kq);
            float2 ax = split2(a.x), ay = split2(a.y), az = split2(a.z), aw = split2(a.w);
            float2 bx = split2(b.x), by = split2(b.y), bz = split2(b.z), bw = split2(b.w);
            int pa = row * GKS + kq * 2;
            *(float4*)&As[pa]     = make_float4(ax.x, ax.y, ay.x, ay.y);
            *(float4*)&As[pa + 4] = make_float4(az.x, az.y, aw.x, aw.y);
            *(float4*)&Bs[pa]     = make_float4(bx.x, bx.y, by.x, by.y);
            *(float4*)&Bs[pa + 4] = make_float4(bz.x, bz.y, bw.x, bw.y);
        }
        __syncthreads();

#pragma unroll
        for (int kk = 0; kk < 32; kk += 8) {
            uint32_t ab[2][4], ar[2][4];
#pragma unroll
            for (int mt = 0; mt < 2; mt++) {
#pragma unroll
                for (int r = 0; r < 4; r++) {
                    int mrow = wm + mt * 16 + g + ((r & 1) ? 8 : 0);
                    int kcol = kk + tk + ((r & 2) ? 4 : 0);
                    float2 v = *(float2*)&As[mrow * GKS + kcol * 2];
                    ab[mt][r] = __float_as_uint(v.x);
                    ar[mt][r] = __float_as_uint(v.y);
                }
            }
#pragma unroll
            for (int nt = 0; nt < 8; nt++) {
                uint32_t bb[2], br[2];
#pragma unroll
                for (int r = 0; r < 2; r++) {
                    int nrow = wn + nt * 8 + g;
                    int kcol = kk + tk + r * 4;
                    float2 v = *(float2*)&Bs[nrow * GKS + kcol * 2];
                    bb[r] = __float_as_uint(v.x);
                    br[r] = __float_as_uint(v.y);
                }
#pragma unroll
                for (int mt = 0; mt < 2; mt++) {
                    mma8(acc[mt][nt], ab[mt], bb);
                    mma8(acc[mt][nt], ar[mt], bb);
                    mma8(acc[mt][nt], ab[mt], br);
                }
            }
        }
        __syncthreads();
    }

#pragma unroll
    for (int mt = 0; mt < 2; mt++) {
#pragma unroll
        for (int nt = 0; nt < 8; nt++) {
            int m = m0 + wm + mt * 16 + g;
            int n = n0 + wn + nt * 8 + 2 * tk;
            float2 v0, v1;
            v0.x = acc[mt][nt][0] * scale; v0.y = acc[mt][nt][1] * scale;
            v1.x = acc[mt][nt][2] * scale; v1.y = acc[mt][nt][3] * scale;
            *(float2*)(C + (size_t)m * N + n) = v0;
            *(float2*)(C + (size_t)(m + 8) * N + n) = v1;
        }
    }
}

// ---------------------------------------------------------------------------
// Flash attention, 3xTF32 tensor-core.
// Grid (QLEN/128, NHEAD, BATCH), 256 thr = 8 warps, warp = 16 query rows.
// K/V tiles (64 keys) split-on-load into smem [key][d*2+b], stride KV_S=136.
// Q staged per-warp, held as register fragments. P via per-warp smem patch.
// ---------------------------------------------------------------------------
#define KV_S 136
#define P_S  68
#define ATT_SMEM ((2 * 64 * KV_S + 8 * 16 * P_S + 64) * 4)   // 104704 B

__global__ __launch_bounds__(256, 1) void attn_tc(const int* __restrict__ mask)
{
    extern __shared__ float sm[];
    float* Ks  = sm;
    float* Vs  = sm + 64 * KV_S;
    float* Ps  = sm + 2 * 64 * KV_S;
    float* pen = Ps + 8 * 16 * P_S;

    const int tid  = threadIdx.x;
    const int lane = tid & 31;
    const int w    = tid >> 5;
    const int g    = lane >> 2;
    const int tk   = lane & 3;
    const int qt = blockIdx.x, h = blockIdx.y, b = blockIdx.z;
    const int q0 = qt * 128;
    const int wrow = w * 16;
    float* Pw = Ps + w * 16 * P_S;

    // ---- Stage this warp's 16 Q rows into its P patch, build tf32 fragments
    {
        const float* Qg = g_Qp + (size_t)(b * QLEN + q0 + wrow) * EMBED + h * HDIM;
#pragma unroll
        for (int it = 0; it < 8; it++) {
            int e = (lane + it * 32) * 4;
            int row = e >> 6, col = e & 63;
            *(float4*)&Pw[row * P_S + col] =
                *(const float4*)(Qg + (size_t)row * EMBED + col);
        }
        __syncwarp();
    }
    uint32_t qb[8][4], qr[8][4];
#pragma unroll
    for (int kk = 0; kk < 8; kk++) {
#pragma unroll
        for (int r = 0; r < 4; r++) {
            int row = ((r & 1) ? g + 8 : g);
            int col = kk * 8 + tk + ((r & 2) ? 4 : 0);
            float2 s2 = split2(Pw[row * P_S + col]);
            qb[kk][r] = __float_as_uint(s2.x);
            qr[kk][r] = __float_as_uint(s2.y);
        }
    }
    __syncwarp();

    float oacc[8][4];
#pragma unroll
    for (int nt = 0; nt < 8; nt++)
#pragma unroll
        for (int r = 0; r < 4; r++) oacc[nt][r] = 0.f;
    float m0 = -INFINITY, m1 = -INFINITY, l0 = 0.f, l1 = 0.f;

    for (int kt = 0; kt < KLEN / 64; kt++) {
        const int k0 = kt * 64;
        __syncthreads();    // prior tile's Ks/Vs/pen reads complete

        // ---- load + split K,V tile: 64 keys x 64 dims each
        const float* Kg = g_Kp + (size_t)(b * KLEN + k0) * EMBED + h * HDIM;
        const float* Vg = g_Vp + (size_t)(b * KLEN + k0) * EMBED + h * HDIM;
#pragma unroll
        for (int it = 0; it < 4; it++) {
            int l = tid + it * 256;
            int key = l >> 4;
            int dq  = (l & 15) * 4;
            float4 kv = *(const float4*)(Kg + (size_t)key * EMBED + dq);
            float4 vv = *(const float4*)(Vg + (size_t)key * EMBED + dq);
            float2 kx = split2(kv.x), ky = split2(kv.y), kz = split2(kv.z), kw = split2(kv.w);
            float2 vx = split2(vv.x), vy = split2(vv.y), vz = split2(vv.z), vw = split2(vv.w);
            int pk = key * KV_S + dq * 2;
            *(float4*)&Ks[pk]     = make_float4(kx.x, kx.y, ky.x, ky.y);
            *(float4*)&Ks[pk + 4] = make_float4(kz.x, kz.y, kw.x, kw.y);
            *(float4*)&Vs[pk]     = make_float4(vx.x, vx.y, vy.x, vy.y);
            *(float4*)&Vs[pk + 4] = make_float4(vz.x, vz.y, vw.x, vw.y);
        }
        if (tid < 64)
            pen[tid] = mask[b * KLEN + k0 + tid] ? 10000.0f : 0.0f;
        __syncthreads();

        // ---- S = Q @ K^T  (16 rows x 64 keys per warp)
        float sacc[8][4];
#pragma unroll
        for (int nt = 0; nt < 8; nt++)
#pragma unroll
            for (int r = 0; r < 4; r++) sacc[nt][r] = 0.f;

#pragma unroll
        for (int kk = 0; kk < 8; kk++) {
#pragma unroll
            for (int nt = 0; nt < 8; nt++) {
                uint32_t kb[2], kr[2];
                float2 v0 = *(float2*)&Ks[(nt * 8 + g) * KV_S + (kk * 8 + tk) * 2];
                float2 v1 = *(float2*)&Ks[(nt * 8 + g) * KV_S + (kk * 8 + tk + 4) * 2];
                kb[0] = __float_as_uint(v0.x); kr[0] = __float_as_uint(v0.y);
                kb[1] = __float_as_uint(v1.x); kr[1] = __float_as_uint(v1.y);
                mma8(sacc[nt], qb[kk], kb);
                mma8(sacc[nt], qr[kk], kb);
                mma8(sacc[nt], qb[kk], kr);
            }
        }

        // ---- mask + online softmax (rows g and g+8 per thread)
        float mx0 = -INFINITY, mx1 = -INFINITY;
#pragma unroll
        for (int nt = 0; nt < 8; nt++) {
            float2 p2 = *(float2*)&pen[nt * 8 + 2 * tk];
            sacc[nt][0] -= p2.x; sacc[nt][1] -= p2.y;
            sacc[nt][2] -= p2.x; sacc[nt][3] -= p2.y;
            mx0 = fmaxf(mx0, fmaxf(sacc[nt][0], sacc[nt][1]));
            mx1 = fmaxf(mx1, fmaxf(sacc[nt][2], sacc[nt][3]));
        }
        mx0 = fmaxf(mx0, __shfl_xor_sync(0xFFFFFFFFu, mx0, 1));
        mx0 = fmaxf(mx0, __shfl_xor_sync(0xFFFFFFFFu, mx0, 2));
        mx1 = fmaxf(mx1, __shfl_xor_sync(0xFFFFFFFFu, mx1, 1));
        mx1 = fmaxf(mx1, __shfl_xor_sync(0xFFFFFFFFu, mx1, 2));

        const float mn0 = fmaxf(m0, mx0), mn1 = fmaxf(m1, mx1);
        const float a0 = __expf(m0 - mn0), a1 = __expf(m1 - mn1);
        float ls0 = 0.f, ls1 = 0.f;
#pragma unroll
        for (int nt = 0; nt < 8; nt++) {
            sacc[nt][0] = __expf(sacc[nt][0] - mn0);
            sacc[nt][1] = __expf(sacc[nt][1] - mn0);
            sacc[nt][2] = __expf(sacc[nt][2] - mn1);
            sacc[nt][3] = __expf(sacc[nt][3] - mn1);
            ls0 += sacc[nt][0] + sacc[nt][1];
            ls1 += sacc[nt][2] + sacc[nt][3];
        }
        ls0 += __shfl_xor_sync(0xFFFFFFFFu, ls0, 1);
        ls0 += __shfl_xor_sync(0xFFFFFFFFu, ls0, 2);
        ls1 += __shfl_xor_sync(0xFFFFFFFFu, ls1, 1);
        ls1 += __shfl_xor_sync(0xFFFFFFFFu, ls1, 2);
        l0 = l0 * a0 + ls0;
        l1 = l1 * a1 + ls1;
        m0 = mn0; m1 = mn1;
#pragma unroll
        for (int nt = 0; nt < 8; nt++) {
            oacc[nt][0] *= a0; oacc[nt][1] *= a0;
            oacc[nt][2] *= a1; oacc[nt][3] *= a1;
        }

        // ---- write P (per-warp patch), then PV
#pragma unroll
        for (int nt = 0; nt < 8; nt++) {
            *(float2*)&Pw[g * P_S + nt * 8 + 2 * tk] =
                make_float2(sacc[nt][0], sacc[nt][1]);
            *(float2*)&Pw[(g + 8) * P_S + nt * 8 + 2 * tk] =
                make_float2(sacc[nt][2], sacc[nt][3]);
        }
        __syncwarp();

#pragma unroll
        for (int kk = 0; kk < 8; kk++) {
            uint32_t pb[4], pr[4];
#pragma unroll
            for (int r = 0; r < 4; r++) {
                int row = ((r & 1) ? g + 8 : g);
                int col = kk * 8 + tk + ((r & 2) ? 4 : 0);
                float2 s2 = split2(Pw[row * P_S + col]);
                pb[r] = __float_as_uint(s2.x);
                pr[r] = __float_as_uint(s2.y);
            }
#pragma unroll
            for (int nt = 0; nt < 8; nt++) {
                uint32_t vb[2], vr[2];
                float2 v0 = *(float2*)&Vs[(kk * 8 + tk) * KV_S + (nt * 8 + g) * 2];
                float2 v1 = *(float2*)&Vs[(kk * 8 + tk + 4) * KV_S + (nt * 8 + g) * 2];
                vb[0] = __float_as_uint(v0.x); vr[0] = __float_as_uint(v0.y);
                vb[1] = __float_as_uint(v1.x); vr[1] = __float_as_uint(v1.y);
                mma8(oacc[nt], pb, vb);
                mma8(oacc[nt], pr, vb);
                mma8(oacc[nt], pb, vr);
            }
        }
        __syncwarp();
    }

    // ---- epilogue
    const float inv0 = 1.0f / l0, inv1 = 1.0f / l1;
    float* o0 = g_ctx + (size_t)(b * QLEN + q0 + wrow + g) * EMBED + h * HDIM;
    float* o1 = g_ctx + (size_t)(b * QLEN + q0 + wrow + g + 8) * EMBED + h * HDIM;
#pragma unroll
    for (int nt = 0; nt < 8; nt++) {
        int d = nt * 8 + 2 * tk;
        *(float2*)(o0 + d) = make_float2(oacc[nt][0] * inv0, oacc[nt][1] * inv0);
        *(float2*)(o1 + d) = make_float2(oacc[nt][2] * inv1, oacc[nt][3] * inv1);
    }
}

// ---------------------------------------------------------------------------
extern "C" void kernel_launch(void* const* d_in, const int* in_sizes, int n_in,
                              void* d_out, int out_size)
{
    (void)in_sizes; (void)n_in; (void)out_size;
    const float* query = (const float*)d_in[0];
    const float* key   = (const float*)d_in[1];
    const float* val   = (const float*)d_in[2];
    const int*   mask  = (const int*)  d_in[3];
    const float* Wq    = (const float*)d_in[4];
    const float* Wk    = (const float*)d_in[5];
    const float* Wv    = (const float*)d_in[6];
    const float* Wo    = (const float*)d_in[7];
    float* out = (float*)d_out;

    float *pQ, *pK, *pV, *pC;
    cudaGetSymbolAddress((void**)&pQ, g_Qp);
    cudaGetSymbolAddress((void**)&pK, g_Kp);
    cudaGetSymbolAddress((void**)&pV, g_Vp);
    cudaGetSymbolAddress((void**)&pC, g_ctx);

    static int attrs_set = 0;
    if (!attrs_set) {
        cudaFuncSetAttribute(gemm_tc,
                             cudaFuncAttributeMaxDynamicSharedMemorySize, GEMM_SMEM);
        cudaFuncSetAttribute(attn_tc,
                             cudaFuncAttributeMaxDynamicSharedMemorySize, ATT_SMEM);
        attrs_set = 1;
    }

    dim3 gGemm(EMBED / 128, MROWS / 128);   // (8, 32)
    const float inv_sqrt_e = 1.0f / 32.0f;  // 1/sqrt(1024), folded into Qp

    gemm_tc<<<gGemm, 256, GEMM_SMEM>>>(query, Wq, pQ, MROWS, EMBED, EMBED, inv_sqrt_e);
    gemm_tc<<<gGemm, 256, GEMM_SMEM>>>(key,   Wk, pK, MROWS, EMBED, EMBED, 1.0f);
    gemm_tc<<<gGemm, 256, GEMM_SMEM>>>(val,   Wv, pV, MROWS, EMBED, EMBED, 1.0f);

    dim3 gAttn(QLEN / 128, NHEAD, BATCH);   // (16, 16, 2)
    attn_tc<<<gAttn, 256, ATT_SMEM>>>(mask);

    gemm_tc<<<gGemm, 256, GEMM_SMEM>>>(pC, Wo, out, MROWS, EMBED, EMBED, 1.0f);
}

// round 4
// speedup vs baseline: 1.8290x; 1.1428x over previous
#include <cuda_runtime.h>
#include <math.h>
#include <stdint.h>

#define EMBED 1024
#define NHEAD 16
#define HDIM  64
#define BATCH 2
#define QLEN  2048
#define KLEN  2048
#define MROWS (BATCH*QLEN)   // 4096
#define K2    (EMBED*2)      // 2048: split row stride in floats

// ---------------------------------------------------------------------------
// Scratch (allocation-free: static device globals). All "2" arrays hold
// interleaved (tf32_big, tf32_res) float pairs.
// ---------------------------------------------------------------------------
__device__ float g_in2[(size_t)3 * MROWS * K2];      // query2,key2,val2
__device__ float g_W2 [(size_t)4 * EMBED * K2];      // Wq2,Wk2,Wv2,Wo2
__device__ float g_Qs2[(size_t)MROWS * K2];
__device__ float g_Ks2[(size_t)MROWS * K2];
__device__ float g_Vs2[(size_t)MROWS * K2];
__device__ float g_ctx2[(size_t)MROWS * K2];
__device__ float g_pen[(size_t)BATCH * KLEN];

// ---------------------------------------------------------------------------
// helpers
// ---------------------------------------------------------------------------
__device__ __forceinline__ uint32_t f2tf(float x) {
    uint32_t r;
    asm("cvt.rna.tf32.f32 %0, %1;" : "=r"(r) : "f"(x));
    return r;
}
__device__ __forceinline__ float2 split2(float x) {
    uint32_t b = f2tf(x);
    float fb = __uint_as_float(b);
    uint32_t r = f2tf(x - fb);
    return make_float2(fb, __uint_as_float(r));
}
__device__ __forceinline__ void mma8(float* c, const uint32_t* a, const uint32_t* b) {
    asm volatile(
        "mma.sync.aligned.m16n8k8.row.col.f32.tf32.tf32.f32 "
        "{%0,%1,%2,%3}, {%4,%5,%6,%7}, {%8,%9}, {%0,%1,%2,%3};\n"
        : "+f"(c[0]), "+f"(c[1]), "+f"(c[2]), "+f"(c[3])
        : "r"(a[0]), "r"(a[1]), "r"(a[2]), "r"(a[3]), "r"(b[0]), "r"(b[1]));
}
__device__ __forceinline__ void cpa16(uint32_t dst, const void* src) {
    asm volatile("cp.async.cg.shared.global [%0], [%1], 16;\n" :: "r"(dst), "l"(src));
}
__device__ __forceinline__ void cpa_commit() {
    asm volatile("cp.async.commit_group;\n");
}
template <int N>
__device__ __forceinline__ void cpa_wait() {
    asm volatile("cp.async.wait_group %0;\n" :: "n"(N));
}

// ---------------------------------------------------------------------------
// prep: split inputs/weights into (big,res) pairs; mask -> penalty floats.
// Units are float4 (of the source). query gets 1/sqrt(EMBED) folded in.
// ---------------------------------------------------------------------------
#define SEG_IN  ((size_t)MROWS * EMBED / 4)     // 1048576 f4 per input tensor
#define SEG_W   ((size_t)EMBED * EMBED / 4)     // 262144 f4 per weight
#define N_IN    (3 * SEG_IN)
#define N_W     (4 * SEG_W)
#define N_MASK  ((size_t)BATCH * KLEN / 4)      // 1024

__global__ __launch_bounds__(256) void prep_split(
    const float* __restrict__ q,  const float* __restrict__ k,
    const float* __restrict__ v,
    const float* __restrict__ wq, const float* __restrict__ wk,
    const float* __restrict__ wv, const float* __restrict__ wo,
    const int* __restrict__ mask)
{
    const size_t total = N_IN + N_W + N_MASK;
    for (size_t u = (size_t)blockIdx.x * blockDim.x + threadIdx.x; u < total;
         u += (size_t)gridDim.x * blockDim.x) {
        if (u < N_IN) {
            int which = (int)(u / SEG_IN);
            size_t off = u - (size_t)which * SEG_IN;
            const float* src = which == 0 ? q : which == 1 ? k : v;
            float sc = which == 0 ? (1.0f / 32.0f) : 1.0f;
            float4 x = ((const float4*)src)[off];
            float2 a = split2(x.x * sc), bb = split2(x.y * sc);
            float2 c = split2(x.z * sc), d  = split2(x.w * sc);
            float4* dst = (float4*)(g_in2 + (size_t)which * MROWS * K2) + off * 2;
            dst[0] = make_float4(a.x, a.y, bb.x, bb.y);
            dst[1] = make_float4(c.x, c.y, d.x, d.y);
        } else if (u < N_IN + N_W) {
            size_t uu = u - N_IN;
            int which = (int)(uu / SEG_W);
            size_t off = uu - (size_t)which * SEG_W;
            const float* src = which == 0 ? wq : which == 1 ? wk
                              : which == 2 ? wv : wo;
            float4 x = ((const float4*)src)[off];
            float2 a = split2(x.x), bb = split2(x.y);
            float2 c = split2(x.z), d  = split2(x.w);
            float4* dst = (float4*)(g_W2 + (size_t)which * EMBED * K2) + off * 2;
            dst[0] = make_float4(a.x, a.y, bb.x, bb.y);
            dst[1] = make_float4(c.x, c.y, d.x, d.y);
        } else {
            size_t off = u - N_IN - N_W;
            int4 m = ((const int4*)mask)[off];
            float4 p;
            p.x = m.x ? 10000.0f : 0.0f;
            p.y = m.y ? 10000.0f : 0.0f;
            p.z = m.z ? 10000.0f : 0.0f;
            p.w = m.w ? 10000.0f : 0.0f;
            ((float4*)g_pen)[off] = p;
        }
    }
}

// ---------------------------------------------------------------------------
// GEMM core: acc = A2 @ W2^T over K=1024, pre-split operands, cp.async
// 2-stage double buffer. Block 128x128, BK=32, 256 thr = 8 warps (4m x 2n).
// smem row stride GKS=72 floats (64 data + 8 pad).
// ---------------------------------------------------------------------------
#define GKS 72
#define GBUF (128 * GKS)                  // floats per buffer per array
#define GEMM_SMEM (4 * GBUF * 4)          // 147456 B

__device__ __forceinline__ void gemm_load_tile(
    uint32_t sbase, int buf, const float* __restrict__ A2,
    const float* __restrict__ W2, int m0, int n0, int t)
{
    const int tid = threadIdx.x;
    const int kof = t * 64;   // floats into split row
#pragma unroll
    for (int it = 0; it < 8; it++) {
        int l = tid + it * 256;
        int row = l >> 4, ch = l & 15;
        uint32_t d = sbase + (uint32_t)((buf * GBUF + row * GKS + ch * 4) * 4);
        cpa16(d, A2 + (size_t)(m0 + row) * K2 + kof + ch * 4);
    }
#pragma unroll
    for (int it = 0; it < 8; it++) {
        int l = tid + it * 256;
        int row = l >> 4, ch = l & 15;
        uint32_t d = sbase + (uint32_t)((2 * GBUF + buf * GBUF + row * GKS + ch * 4) * 4);
        cpa16(d, W2 + (size_t)(n0 + row) * K2 + kof + ch * 4);
    }
}

__device__ __forceinline__ void gemm_core(
    const float* __restrict__ A2, const float* __restrict__ W2,
    float* sm, float acc[2][8][4], int m0, int n0)
{
    const int tid  = threadIdx.x;
    const int lane = tid & 31;
    const int w    = tid >> 5;
    const int g    = lane >> 2;
    const int tk   = lane & 3;
    const int wm   = (w & 3) * 32;
    const int wn   = (w >> 2) * 64;
    uint32_t sbase = (uint32_t)__cvta_generic_to_shared(sm);

#pragma unroll
    for (int mt = 0; mt < 2; mt++)
#pragma unroll
        for (int nt = 0; nt < 8; nt++)
#pragma unroll
            for (int r = 0; r < 4; r++) acc[mt][nt][r] = 0.f;

    const int T = EMBED / 32;   // 32 tiles
    gemm_load_tile(sbase, 0, A2, W2, m0, n0, 0);
    cpa_commit();

    for (int t = 0; t < T; t++) {
        if (t + 1 < T) {
            gemm_load_tile(sbase, (t + 1) & 1, A2, W2, m0, n0, t + 1);
            cpa_commit();
            cpa_wait<1>();
        } else {
            cpa_wait<0>();
        }
        __syncthreads();

        const float* As = sm + (t & 1) * GBUF;
        const float* Bs = sm + 2 * GBUF + (t & 1) * GBUF;
#pragma unroll
        for (int kk = 0; kk < 32; kk += 8) {
            uint32_t ab[2][4], ar[2][4];
#pragma unroll
            for (int mt = 0; mt < 2; mt++) {
#pragma unroll
                for (int r = 0; r < 4; r++) {
                    int mrow = wm + mt * 16 + g + ((r & 1) ? 8 : 0);
                    int kcol = kk + tk + ((r & 2) ? 4 : 0);
                    float2 vv = *(const float2*)&As[mrow * GKS + kcol * 2];
                    ab[mt][r] = __float_as_uint(vv.x);
                    ar[mt][r] = __float_as_uint(vv.y);
                }
            }
#pragma unroll
            for (int nt = 0; nt < 8; nt++) {
                uint32_t bb[2], br[2];
#pragma unroll
                for (int r = 0; r < 2; r++) {
                    int nrow = wn + nt * 8 + g;
                    int kcol = kk + tk + r * 4;
                    float2 vv = *(const float2*)&Bs[nrow * GKS + kcol * 2];
                    bb[r] = __float_as_uint(vv.x);
                    br[r] = __float_as_uint(vv.y);
                }
#pragma unroll
                for (int mt = 0; mt < 2; mt++) {
                    mma8(acc[mt][nt], ab[mt], bb);
                    mma8(acc[mt][nt], ar[mt], bb);
                    mma8(acc[mt][nt], ab[mt], br);
                }
            }
        }
        __syncthreads();
    }
}

// QKV projections fused: z = 0/1/2 selects input, weight, split output.
__global__ __launch_bounds__(256) void gemm_qkv()
{
    extern __shared__ float sm[];
    const int z = blockIdx.z;
    const float* A2 = g_in2 + (size_t)z * MROWS * K2;
    const float* W2 = g_W2 + (size_t)z * EMBED * K2;
    float* C2 = z == 0 ? g_Qs2 : z == 1 ? g_Ks2 : g_Vs2;
    const int m0 = blockIdx.y * 128;
    const int n0 = blockIdx.x * 128;

    float acc[2][8][4];
    gemm_core(A2, W2, sm, acc, m0, n0);

    const int lane = threadIdx.x & 31;
    const int w    = threadIdx.x >> 5;
    const int g    = lane >> 2;
    const int tk   = lane & 3;
    const int wm   = (w & 3) * 32;
    const int wn   = (w >> 2) * 64;
#pragma unroll
    for (int mt = 0; mt < 2; mt++) {
#pragma unroll
        for (int nt = 0; nt < 8; nt++) {
            int m = m0 + wm + mt * 16 + g;
            int n = n0 + wn + nt * 8 + 2 * tk;
            float2 s0 = split2(acc[mt][nt][0]), s1 = split2(acc[mt][nt][1]);
            float2 s2 = split2(acc[mt][nt][2]), s3 = split2(acc[mt][nt][3]);
            *(float4*)(C2 + (size_t)m * K2 + n * 2) =
                make_float4(s0.x, s0.y, s1.x, s1.y);
            *(float4*)(C2 + (size_t)(m + 8) * K2 + n * 2) =
                make_float4(s2.x, s2.y, s3.x, s3.y);
        }
    }
}

// Output projection: ctx2 @ Wo2^T -> plain fp32 out.
__global__ __launch_bounds__(256) void gemm_out(float* __restrict__ out)
{
    extern __shared__ float sm[];
    const float* A2 = g_ctx2;
    const float* W2 = g_W2 + (size_t)3 * EMBED * K2;
    const int m0 = blockIdx.y * 128;
    const int n0 = blockIdx.x * 128;

    float acc[2][8][4];
    gemm_core(A2, W2, sm, acc, m0, n0);

    const int lane = threadIdx.x & 31;
    const int w    = threadIdx.x >> 5;
    const int g    = lane >> 2;
    const int tk   = lane & 3;
    const int wm   = (w & 3) * 32;
    const int wn   = (w >> 2) * 64;
#pragma unroll
    for (int mt = 0; mt < 2; mt++) {
#pragma unroll
        for (int nt = 0; nt < 8; nt++) {
            int m = m0 + wm + mt * 16 + g;
            int n = n0 + wn + nt * 8 + 2 * tk;
            *(float2*)(out + (size_t)m * EMBED + n) =
                make_float2(acc[mt][nt][0], acc[mt][nt][1]);
            *(float2*)(out + (size_t)(m + 8) * EMBED + n) =
                make_float2(acc[mt][nt][2], acc[mt][nt][3]);
        }
    }
}

// ---------------------------------------------------------------------------
// Flash attention, 3xTF32, pre-split operands, cp.async double-buffered K/V.
// Grid (QLEN/128, NHEAD, BATCH), 256 thr = 8 warps, warp = 16 query rows.
// ---------------------------------------------------------------------------
#define KV_S 136
#define KVBUF (64 * KV_S)                  // 8704 floats
#define P_S  68
#define OFF_V  (2 * KVBUF)                 // 17408
#define OFF_P  (4 * KVBUF)                 // 34816
#define OFF_PEN (OFF_P + 8 * 16 * P_S)     // 43520
#define ATT_SMEM ((OFF_PEN + 2 * 64) * 4)  // 174592 B

__device__ __forceinline__ void attn_load_tile(uint32_t sbase, int buf,
                                               int b, int h, int kt)
{
    const int tid = threadIdx.x;
    const float* Kg = g_Ks2 + ((size_t)(b * KLEN + kt * 64)) * K2 + h * HDIM * 2;
    const float* Vg = g_Vs2 + ((size_t)(b * KLEN + kt * 64)) * K2 + h * HDIM * 2;
#pragma unroll
    for (int it = 0; it < 8; it++) {
        int l = tid + it * 256;
        int row = l >> 5, ch = l & 31;
        uint32_t dK = sbase + (uint32_t)((buf * KVBUF + row * KV_S + ch * 4) * 4);
        cpa16(dK, Kg + (size_t)row * K2 + ch * 4);
        uint32_t dV = sbase + (uint32_t)((OFF_V + buf * KVBUF + row * KV_S + ch * 4) * 4);
        cpa16(dV, Vg + (size_t)row * K2 + ch * 4);
    }
    if (tid < 16)
        cpa16(sbase + (uint32_t)((OFF_PEN + buf * 64 + tid * 4) * 4),
              g_pen + (size_t)b * KLEN + kt * 64 + tid * 4);
}

__global__ __launch_bounds__(256, 1) void attn_tc()
{
    extern __shared__ float sm[];
    uint32_t sbase = (uint32_t)__cvta_generic_to_shared(sm);

    const int tid  = threadIdx.x;
    const int lane = tid & 31;
    const int w    = tid >> 5;
    const int g    = lane >> 2;
    const int tk   = lane & 3;
    const int qt = blockIdx.x, h = blockIdx.y, b = blockIdx.z;
    const int q0 = qt * 128;
    const int wrow = w * 16;
    float* Pw = sm + OFF_P + w * 16 * P_S;

    // ---- Q fragments straight from pre-split gmem
    uint32_t qb[8][4], qr[8][4];
    {
        const float* Qg = g_Qs2 + (size_t)(b * QLEN + q0 + wrow) * K2 + h * HDIM * 2;
#pragma unroll
        for (int kk = 0; kk < 8; kk++) {
#pragma unroll
            for (int r = 0; r < 4; r++) {
                int row = g + ((r & 1) ? 8 : 0);
                int col = kk * 8 + tk + ((r & 2) ? 4 : 0);
                float2 vv = *(const float2*)(Qg + (size_t)row * K2 + col * 2);
                qb[kk][r] = __float_as_uint(vv.x);
                qr[kk][r] = __float_as_uint(vv.y);
            }
        }
    }

    float oacc[8][4];
#pragma unroll
    for (int nt = 0; nt < 8; nt++)
#pragma unroll
        for (int r = 0; r < 4; r++) oacc[nt][r] = 0.f;
    float m0 = -INFINITY, m1 = -INFINITY, l0 = 0.f, l1 = 0.f;

    const int T = KLEN / 64;
    attn_load_tile(sbase, 0, b, h, 0);
    cpa_commit();

    for (int kt = 0; kt < T; kt++) {
        if (kt + 1 < T) {
            attn_load_tile(sbase, (kt + 1) & 1, b, h, kt + 1);
            cpa_commit();
            cpa_wait<1>();
        } else {
            cpa_wait<0>();
        }
        __syncthreads();

        const float* Ks  = sm + (kt & 1) * KVBUF;
        const float* Vs  = sm + OFF_V + (kt & 1) * KVBUF;
        const float* pen = sm + OFF_PEN + (kt & 1) * 64;

        // ---- S = Q @ K^T
        float sacc[8][4];
#pragma unroll
        for (int nt = 0; nt < 8; nt++)
#pragma unroll
            for (int r = 0; r < 4; r++) sacc[nt][r] = 0.f;

#pragma unroll
        for (int kk = 0; kk < 8; kk++) {
#pragma unroll
            for (int nt = 0; nt < 8; nt++) {
                uint32_t kb[2], kr[2];
                float2 v0 = *(const float2*)&Ks[(nt * 8 + g) * KV_S + (kk * 8 + tk) * 2];
                float2 v1 = *(const float2*)&Ks[(nt * 8 + g) * KV_S + (kk * 8 + tk + 4) * 2];
                kb[0] = __float_as_uint(v0.x); kr[0] = __float_as_uint(v0.y);
                kb[1] = __float_as_uint(v1.x); kr[1] = __float_as_uint(v1.y);
                mma8(sacc[nt], qb[kk], kb);
                mma8(sacc[nt], qr[kk], kb);
                mma8(sacc[nt], qb[kk], kr);
            }
        }

        // ---- mask + online softmax (rows g, g+8)
        float mx0 = -INFINITY, mx1 = -INFINITY;
#pragma unroll
        for (int nt = 0; nt < 8; nt++) {
            float2 p2 = *(const float2*)&pen[nt * 8 + 2 * tk];
            sacc[nt][0] -= p2.x; sacc[nt][1] -= p2.y;
            sacc[nt][2] -= p2.x; sacc[nt][3] -= p2.y;
            mx0 = fmaxf(mx0, fmaxf(sacc[nt][0], sacc[nt][1]));
            mx1 = fmaxf(mx1, fmaxf(sacc[nt][2], sacc[nt][3]));
        }
        mx0 = fmaxf(mx0, __shfl_xor_sync(0xFFFFFFFFu, mx0, 1));
        mx0 = fmaxf(mx0, __shfl_xor_sync(0xFFFFFFFFu, mx0, 2));
        mx1 = fmaxf(mx1, __shfl_xor_sync(0xFFFFFFFFu, mx1, 1));
        mx1 = fmaxf(mx1, __shfl_xor_sync(0xFFFFFFFFu, mx1, 2));

        const float mn0 = fmaxf(m0, mx0), mn1 = fmaxf(m1, mx1);
        const float a0 = __expf(m0 - mn0), a1 = __expf(m1 - mn1);
        float ls0 = 0.f, ls1 = 0.f;
#pragma unroll
        for (int nt = 0; nt < 8; nt++) {
            sacc[nt][0] = __expf(sacc[nt][0] - mn0);
            sacc[nt][1] = __expf(sacc[nt][1] - mn0);
            sacc[nt][2] = __expf(sacc[nt][2] - mn1);
            sacc[nt][3] = __expf(sacc[nt][3] - mn1);
            ls0 += sacc[nt][0] + sacc[nt][1];
            ls1 += sacc[nt][2] + sacc[nt][3];
        }
        ls0 += __shfl_xor_sync(0xFFFFFFFFu, ls0, 1);
        ls0 += __shfl_xor_sync(0xFFFFFFFFu, ls0, 2);
        ls1 += __shfl_xor_sync(0xFFFFFFFFu, ls1, 1);
        ls1 += __shfl_xor_sync(0xFFFFFFFFu, ls1, 2);
        l0 = l0 * a0 + ls0;
        l1 = l1 * a1 + ls1;
        m0 = mn0; m1 = mn1;
#pragma unroll
        for (int nt = 0; nt < 8; nt++) {
            oacc[nt][0] *= a0; oacc[nt][1] *= a0;
            oacc[nt][2] *= a1; oacc[nt][3] *= a1;
        }

        // ---- P through per-warp smem patch, then PV
#pragma unroll
        for (int nt = 0; nt < 8; nt++) {
            *(float2*)&Pw[g * P_S + nt * 8 + 2 * tk] =
                make_float2(sacc[nt][0], sacc[nt][1]);
            *(float2*)&Pw[(g + 8) * P_S + nt * 8 + 2 * tk] =
                make_float2(sacc[nt][2], sacc[nt][3]);
        }
        __syncwarp();

#pragma unroll
        for (int kk = 0; kk < 8; kk++) {
            uint32_t pb[4], pr[4];
#pragma unroll
            for (int r = 0; r < 4; r++) {
                int row = ((r & 1) ? g + 8 : g);
                int col = kk * 8 + tk + ((r & 2) ? 4 : 0);
                float2 s2 = split2(Pw[row * P_S + col]);
                pb[r] = __float_as_uint(s2.x);
                pr[r] = __float_as_uint(s2.y);
            }
#pragma unroll
            for (int nt = 0; nt < 8; nt++) {
                uint32_t vb[2], vr[2];
                float2 v0 = *(const float2*)&Vs[(kk * 8 + tk) * KV_S + (nt * 8 + g) * 2];
                float2 v1 = *(const float2*)&Vs[(kk * 8 + tk + 4) * KV_S + (nt * 8 + g) * 2];
                vb[0] = __float_as_uint(v0.x); vr[0] = __float_as_uint(v0.y);
                vb[1] = __float_as_uint(v1.x); vr[1] = __float_as_uint(v1.y);
                mma8(oacc[nt], pb, vb);
                mma8(oacc[nt], pr, vb);
                mma8(oacc[nt], pb, vr);
            }
        }
        __syncwarp();
        __syncthreads();
    }

    // ---- epilogue: write split ctx for the output GEMM
    const float inv0 = 1.0f / l0, inv1 = 1.0f / l1;
    float* o0 = g_ctx2 + (size_t)(b * QLEN + q0 + wrow + g) * K2 + h * HDIM * 2;
    float* o1 = g_ctx2 + (size_t)(b * QLEN + q0 + wrow + g + 8) * K2 + h * HDIM * 2;
#pragma unroll
    for (int nt = 0; nt < 8; nt++) {
        int d = nt * 8 + 2 * tk;
        float2 s0 = split2(oacc[nt][0] * inv0), s1 = split2(oacc[nt][1] * inv0);
        float2 s2 = split2(oacc[nt][2] * inv1), s3 = split2(oacc[nt][3] * inv1);
        *(float4*)(o0 + d * 2) = make_float4(s0.x, s0.y, s1.x, s1.y);
        *(float4*)(o1 + d * 2) = make_float4(s2.x, s2.y, s3.x, s3.y);
    }
}

// ---------------------------------------------------------------------------
extern "C" void kernel_launch(void* const* d_in, const int* in_sizes, int n_in,
                              void* d_out, int out_size)
{
    (void)in_sizes; (void)n_in; (void)out_size;
    const float* query = (const float*)d_in[0];
    const float* key   = (const float*)d_in[1];
    const float* val   = (const float*)d_in[2];
    const int*   mask  = (const int*)  d_in[3];
    const float* Wq    = (const float*)d_in[4];
    const float* Wk    = (const float*)d_in[5];
    const float* Wv    = (const float*)d_in[6];
    const float* Wo    = (const float*)d_in[7];
    float* out = (float*)d_out;

    static int attrs_set = 0;
    if (!attrs_set) {
        cudaFuncSetAttribute(gemm_qkv,
                             cudaFuncAttributeMaxDynamicSharedMemorySize, GEMM_SMEM);
        cudaFuncSetAttribute(gemm_out,
                             cudaFuncAttributeMaxDynamicSharedMemorySize, GEMM_SMEM);
        cudaFuncSetAttribute(attn_tc,
                             cudaFuncAttributeMaxDynamicSharedMemorySize, ATT_SMEM);
        attrs_set = 1;
    }

    prep_split<<<2048, 256>>>(query, key, val, Wq, Wk, Wv, Wo, mask);

    dim3 gQKV(EMBED / 128, MROWS / 128, 3);     // (8, 32, 3)
    gemm_qkv<<<gQKV, 256, GEMM_SMEM>>>();

    dim3 gAttn(QLEN / 128, NHEAD, BATCH);       // (16, 16, 2)
    attn_tc<<<gAttn, 256, ATT_SMEM>>>();

    dim3 gOut(EMBED / 128, MROWS / 128);        // (8, 32)
    gemm_out<<<gOut, 256, GEMM_SMEM>>>(out);
}

// round 6
// speedup vs baseline: 3.7558x; 2.0535x over previous
#include <cuda_runtime.h>
#include <math.h>
#include <stdint.h>

#define EMBED 1024
#define NHEAD 16
#define HDIM  64
#define BATCH 2
#define QLEN  2048
#define KLEN  2048
#define MROWS (BATCH*QLEN)   // 4096
#define RU    1024           // u32 per packed row (1 u32 per element)

// ---------------------------------------------------------------------------
// Packed split-bf16 format: elements are stored in pairs along the pack axis.
// Pair p occupies u32[2p] = bf16x2(hi(x0),hi(x1)) and u32[2p+1] = bf16x2 of lo.
// => exactly 1 u32 per element, pairs are 8B-aligned for LDS.64 / uint2.
// ---------------------------------------------------------------------------
__device__ uint32_t g_in2[(size_t)3 * MROWS * RU];           // query2,key2,val2
__device__ uint32_t g_W2 [(size_t)4 * EMBED * RU];           // Wq2,Wk2,Wv2,Wo2
__device__ uint32_t g_Qb [(size_t)MROWS * RU];               // packed along d
__device__ uint32_t g_Kb [(size_t)MROWS * RU];               // packed along d
__device__ uint32_t g_Vb [(size_t)BATCH * NHEAD * HDIM * KLEN]; // [b][h][d][key-pairs]
__device__ uint32_t g_Cb [(size_t)MROWS * RU];               // ctx, packed along d
__device__ float    g_pen[(size_t)BATCH * KLEN];

// ---------------------------------------------------------------------------
// helpers
// ---------------------------------------------------------------------------
__device__ __forceinline__ void packsplit(float x0, float x1,
                                          uint32_t& hi, uint32_t& lo) {
    uint32_t h;
    asm("cvt.rn.bf16x2.f32 %0, %1, %2;" : "=r"(h) : "f"(x1), "f"(x0));
    float h0 = __uint_as_float(h << 16);
    float h1 = __uint_as_float(h & 0xffff0000u);
    float l0 = x0 - h0, l1 = x1 - h1;
    uint32_t l;
    asm("cvt.rn.bf16x2.f32 %0, %1, %2;" : "=r"(l) : "f"(l1), "f"(l0));
    hi = h; lo = l;
}

__device__ __forceinline__ void mma16(float* c, const uint32_t* a, const uint32_t* b) {
    asm volatile(
        "mma.sync.aligned.m16n8k16.row.col.f32.bf16.bf16.f32 "
        "{%0,%1,%2,%3}, {%4,%5,%6,%7}, {%8,%9}, {%0,%1,%2,%3};\n"
        : "+f"(c[0]), "+f"(c[1]), "+f"(c[2]), "+f"(c[3])
        : "r"(a[0]), "r"(a[1]), "r"(a[2]), "r"(a[3]), "r"(b[0]), "r"(b[1]));
}

__device__ __forceinline__ void cpa16(uint32_t dst, const void* src) {
    asm volatile("cp.async.cg.shared.global [%0], [%1], 16;\n" :: "r"(dst), "l"(src));
}
__device__ __forceinline__ void cpa_commit() {
    asm volatile("cp.async.commit_group;\n");
}
template <int N>
__device__ __forceinline__ void cpa_wait() {
    asm volatile("cp.async.wait_group %0;\n" :: "n"(N));
}

// ---------------------------------------------------------------------------
// prep: split inputs/weights into packed split-bf16; mask -> penalty floats.
// One unit = one source float4 (= 2 pairs = uint4 out).
// ---------------------------------------------------------------------------
#define SEG_IN  ((size_t)MROWS * EMBED / 4)
#define SEG_W   ((size_t)EMBED * EMBED / 4)
#define N_IN    (3 * SEG_IN)
#define N_W     (4 * SEG_W)
#define N_MASK  ((size_t)BATCH * KLEN / 4)

__global__ __launch_bounds__(256) void prep_split(
    const float* __restrict__ q,  const float* __restrict__ k,
    const float* __restrict__ v,
    const float* __restrict__ wq, const float* __restrict__ wk,
    const float* __restrict__ wv, const float* __restrict__ wo,
    const int* __restrict__ mask)
{
    const size_t total = N_IN + N_W + N_MASK;
    for (size_t u = (size_t)blockIdx.x * blockDim.x + threadIdx.x; u < total;
         u += (size_t)gridDim.x * blockDim.x) {
        if (u < N_IN) {
            int which = (int)(u / SEG_IN);
            size_t off = u - (size_t)which * SEG_IN;
            const float* src = which == 0 ? q : which == 1 ? k : v;
            float sc = which == 0 ? (1.0f / 32.0f) : 1.0f;
            float4 x = ((const float4*)src)[off];
            uint4 o;
            packsplit(x.x * sc, x.y * sc, o.x, o.y);
            packsplit(x.z * sc, x.w * sc, o.z, o.w);
            ((uint4*)(g_in2 + (size_t)which * MROWS * RU))[off] = o;
        } else if (u < N_IN + N_W) {
            size_t uu = u - N_IN;
            int which = (int)(uu / SEG_W);
            size_t off = uu - (size_t)which * SEG_W;
            const float* src = which == 0 ? wq : which == 1 ? wk
                              : which == 2 ? wv : wo;
            float4 x = ((const float4*)src)[off];
            uint4 o;
            packsplit(x.x, x.y, o.x, o.y);
            packsplit(x.z, x.w, o.z, o.w);
            ((uint4*)(g_W2 + (size_t)which * EMBED * RU))[off] = o;
        } else {
            size_t off = u - N_IN - N_W;
            int4 m = ((const int4*)mask)[off];
            float4 p;
            p.x = m.x ? 10000.0f : 0.0f;
            p.y = m.y ? 10000.0f : 0.0f;
            p.z = m.z ? 10000.0f : 0.0f;
            p.w = m.w ? 10000.0f : 0.0f;
            ((float4*)g_pen)[off] = p;
        }
    }
}

// ---------------------------------------------------------------------------
// GEMM core: acc = A2 @ W2^T over K=1024. Packed split-bf16 operands,
// cp.async 2-stage double buffer. 128x128 tile, BK=32 elems (32 u32/row),
// 256 thr = 8 warps (4m x 2n), warp 32x64. smem row stride 40 u32 (8 mod 32
// => 8g bank pattern, conflict-free LDS.64 for fragments).
// ---------------------------------------------------------------------------
#define RG 40
#define GBUFU (128 * RG)                       // 5120 u32 per buffer
#define GEMM_SMEM (4 * GBUFU * 4)              // 81920 B

__device__ __forceinline__ void gemm_load_tile(
    uint32_t sbase, int buf, const uint32_t* __restrict__ A2,
    const uint32_t* __restrict__ W2, int m0, int n0, int t)
{
    const int tid = threadIdx.x;
    const int kof = t * 32;
#pragma unroll
    for (int it = 0; it < 4; it++) {
        int l = tid + it * 256;
        int row = l >> 3, c = l & 7;
        cpa16(sbase + (uint32_t)((buf * GBUFU + row * RG + c * 4) * 4),
              A2 + (size_t)(m0 + row) * RU + kof + c * 4);
    }
#pragma unroll
    for (int it = 0; it < 4; it++) {
        int l = tid + it * 256;
        int row = l >> 3, c = l & 7;
        cpa16(sbase + (uint32_t)((2 * GBUFU + buf * GBUFU + row * RG + c * 4) * 4),
              W2 + (size_t)(n0 + row) * RU + kof + c * 4);
    }
}

__device__ __forceinline__ void gemm_core(
    const uint32_t* __restrict__ A2, const uint32_t* __restrict__ W2,
    uint32_t* smu, float acc[2][8][4], int m0, int n0)
{
    const int tid  = threadIdx.x;
    const int lane = tid & 31;
    const int w    = tid >> 5;
    const int g    = lane >> 2;
    const int tk   = lane & 3;
    const int wm   = (w & 3) * 32;
    const int wn   = (w >> 2) * 64;
    uint32_t sbase = (uint32_t)__cvta_generic_to_shared(smu);

#pragma unroll
    for (int mt = 0; mt < 2; mt++)
#pragma unroll
        for (int nt = 0; nt < 8; nt++)
#pragma unroll
            for (int r = 0; r < 4; r++) acc[mt][nt][r] = 0.f;

    const int T = EMBED / 32;   // 32 k-tiles
    gemm_load_tile(sbase, 0, A2, W2, m0, n0, 0);
    cpa_commit();

    for (int t = 0; t < T; t++) {
        if (t + 1 < T) {
            gemm_load_tile(sbase, (t + 1) & 1, A2, W2, m0, n0, t + 1);
            cpa_commit();
            cpa_wait<1>();
        } else {
            cpa_wait<0>();
        }
        __syncthreads();

        const uint32_t* As = smu + (t & 1) * GBUFU;
        const uint32_t* Bs = smu + 2 * GBUFU + (t & 1) * GBUFU;
#pragma unroll
        for (int kk = 0; kk < 2; kk++) {
            uint32_t ah[2][4], al[2][4];
#pragma unroll
            for (int mt = 0; mt < 2; mt++) {
                int rb = wm + mt * 16;
                int cb = kk * 16 + 2 * tk;
                uint2 v;
                v = *(const uint2*)&As[(rb + g) * RG + cb];
                ah[mt][0] = v.x; al[mt][0] = v.y;
                v = *(const uint2*)&As[(rb + g + 8) * RG + cb];
                ah[mt][1] = v.x; al[mt][1] = v.y;
                v = *(const uint2*)&As[(rb + g) * RG + cb + 8];
                ah[mt][2] = v.x; al[mt][2] = v.y;
                v = *(const uint2*)&As[(rb + g + 8) * RG + cb + 8];
                ah[mt][3] = v.x; al[mt][3] = v.y;
            }
#pragma unroll
            for (int nt = 0; nt < 8; nt++) {
                int cb = kk * 16 + 2 * tk;
                uint2 b0 = *(const uint2*)&Bs[(wn + nt * 8 + g) * RG + cb];
                uint2 b1 = *(const uint2*)&Bs[(wn + nt * 8 + g) * RG + cb + 8];
                uint32_t bh[2] = {b0.x, b1.x};
                uint32_t bl[2] = {b0.y, b1.y};
#pragma unroll
                for (int mt = 0; mt < 2; mt++) {
                    mma16(acc[mt][nt], ah[mt], bh);
                    mma16(acc[mt][nt], al[mt], bh);
                    mma16(acc[mt][nt], ah[mt], bl);
                }
            }
        }
        __syncthreads();
    }
}

// QKV projections fused: z = 0 (Q), 1 (K), 2 (V, transposed split output).
__global__ __launch_bounds__(256, 2) void gemm_qkv()
{
    extern __shared__ uint32_t smu[];
    const int z = blockIdx.z;
    const uint32_t* A2 = g_in2 + (size_t)z * MROWS * RU;
    const uint32_t* W2 = g_W2 + (size_t)z * EMBED * RU;
    const int m0 = blockIdx.y * 128;
    const int n0 = blockIdx.x * 128;

    float acc[2][8][4];
    gemm_core(A2, W2, smu, acc, m0, n0);

    const int lane = threadIdx.x & 31;
    const int w    = threadIdx.x >> 5;
    const int g    = lane >> 2;
    const int tk   = lane & 3;
    const int wm   = (w & 3) * 32;
    const int wn   = (w >> 2) * 64;

    if (z < 2) {
        uint32_t* C2 = z == 0 ? g_Qb : g_Kb;
#pragma unroll
        for (int mt = 0; mt < 2; mt++) {
#pragma unroll
            for (int nt = 0; nt < 8; nt++) {
                int m = m0 + wm + mt * 16 + g;
                int n = n0 + wn + nt * 8 + 2 * tk;
                uint2 o;
                packsplit(acc[mt][nt][0], acc[mt][nt][1], o.x, o.y);
                *(uint2*)(C2 + (size_t)m * RU + n) = o;
                packsplit(acc[mt][nt][2], acc[mt][nt][3], o.x, o.y);
                *(uint2*)(C2 + (size_t)(m + 8) * RU + n) = o;
            }
        }
    } else {
        // V: write [b][h][d][key-pairs]; pair keys (g even, g odd) via shfl.
#pragma unroll
        for (int mt = 0; mt < 2; mt++) {
#pragma unroll
            for (int nt = 0; nt < 8; nt++) {
                float c0 = acc[mt][nt][0], c1 = acc[mt][nt][1];
                float c2 = acc[mt][nt][2], c3 = acc[mt][nt][3];
                float oc0 = __shfl_xor_sync(0xFFFFFFFFu, c0, 4);
                float oc1 = __shfl_xor_sync(0xFFFFFFFFu, c1, 4);
                float oc2 = __shfl_xor_sync(0xFFFFFFFFu, c2, 4);
                float oc3 = __shfl_xor_sync(0xFFFFFFFFu, c3, 4);
                if (!(g & 1)) {
                    int m = m0 + wm + mt * 16 + g;   // even key
                    int n = n0 + wn + nt * 8 + 2 * tk;
                    int b = m >> 11, key = m & 2047;
                    int hh = n >> 6, dl = n & 63;
                    uint32_t* base =
                        g_Vb + ((size_t)((b * NHEAD + hh) * HDIM + dl)) * KLEN;
                    uint2 o;
                    packsplit(c0, oc0, o.x, o.y);
                    *(uint2*)(base + key) = o;
                    packsplit(c2, oc2, o.x, o.y);
                    *(uint2*)(base + key + 8) = o;
                    packsplit(c1, oc1, o.x, o.y);
                    *(uint2*)(base + KLEN + key) = o;
                    packsplit(c3, oc3, o.x, o.y);
                    *(uint2*)(base + KLEN + key + 8) = o;
                }
            }
        }
    }
}

// Output projection: ctx2 @ Wo2^T -> plain fp32 out.
__global__ __launch_bounds__(256, 2) void gemm_out(float* __restrict__ out)
{
    extern __shared__ uint32_t smu[];
    const uint32_t* W2 = g_W2 + (size_t)3 * EMBED * RU;
    const int m0 = blockIdx.y * 128;
    const int n0 = blockIdx.x * 128;

    float acc[2][8][4];
    gemm_core(g_Cb, W2, smu, acc, m0, n0);

    const int lane = threadIdx.x & 31;
    const int w    = threadIdx.x >> 5;
    const int g    = lane >> 2;
    const int tk   = lane & 3;
    const int wm   = (w & 3) * 32;
    const int wn   = (w >> 2) * 64;
#pragma unroll
    for (int mt = 0; mt < 2; mt++) {
#pragma unroll
        for (int nt = 0; nt < 8; nt++) {
            int m = m0 + wm + mt * 16 + g;
            int n = n0 + wn + nt * 8 + 2 * tk;
            *(float2*)(out + (size_t)m * EMBED + n) =
                make_float2(acc[mt][nt][0], acc[mt][nt][1]);
            *(float2*)(out + (size_t)(m + 8) * EMBED + n) =
                make_float2(acc[mt][nt][2], acc[mt][nt][3]);
        }
    }
}

// ---------------------------------------------------------------------------
// Flash attention, split-bf16. Grid (QLEN/128, NHEAD, BATCH), 256 thr,
// 8 warps x 16 q-rows. K smem [key][d-pairs], V smem [d][key-pairs],
// both row stride 72 u32, double-buffered via cp.async. P = direct
// S-accumulator repack (C-frag == A-frag layout for m16n8k16).
// ---------------------------------------------------------------------------
#define RA 72
#define ABUFU (64 * RA)                        // 4608 u32
#define ATT_SMEM (4 * ABUFU * 4)               // 73728 B

__device__ __forceinline__ void attn_load_tile(uint32_t sbase, int buf,
                                               int b, int h, int kt)
{
    const int tid = threadIdx.x;
    const uint32_t* Kg = g_Kb + (size_t)(b * KLEN + kt * 64) * RU + h * HDIM;
    const uint32_t* Vg = g_Vb + ((size_t)(b * NHEAD + h) * HDIM) * KLEN + kt * 64;
#pragma unroll
    for (int it = 0; it < 4; it++) {
        int l = tid + it * 256;
        int row = l >> 4, c = l & 15;
        cpa16(sbase + (uint32_t)((buf * ABUFU + row * RA + c * 4) * 4),
              Kg + (size_t)row * RU + c * 4);
        cpa16(sbase + (uint32_t)((2 * ABUFU + buf * ABUFU + row * RA + c * 4) * 4),
              Vg + (size_t)row * KLEN + c * 4);
    }
}

__global__ __launch_bounds__(256, 2) void attn_tc()
{
    extern __shared__ uint32_t smu[];
    uint32_t sbase = (uint32_t)__cvta_generic_to_shared(smu);

    const int tid  = threadIdx.x;
    const int lane = tid & 31;
    const int w    = tid >> 5;
    const int g    = lane >> 2;
    const int tk   = lane & 3;
    const int qt = blockIdx.x, h = blockIdx.y, b = blockIdx.z;
    const int q0 = qt * 128;
    const int wrow = w * 16;

    // ---- Q fragments from packed gmem (held in regs for all tiles)
    uint32_t qh[4][4], ql[4][4];
    {
        const uint32_t* Qg = g_Qb + (size_t)(b * QLEN + q0 + wrow) * RU + h * HDIM;
#pragma unroll
        for (int kk = 0; kk < 4; kk++) {
            int cb = kk * 16 + 2 * tk;
            uint2 v;
            v = *(const uint2*)(Qg + (size_t)g * RU + cb);
            qh[kk][0] = v.x; ql[kk][0] = v.y;
            v = *(const uint2*)(Qg + (size_t)(g + 8) * RU + cb);
            qh[kk][1] = v.x; ql[kk][1] = v.y;
            v = *(const uint2*)(Qg + (size_t)g * RU + cb + 8);
            qh[kk][2] = v.x; ql[kk][2] = v.y;
            v = *(const uint2*)(Qg + (size_t)(g + 8) * RU + cb + 8);
            qh[kk][3] = v.x; ql[kk][3] = v.y;
        }
    }

    float oacc[8][4];
#pragma unroll
    for (int nt = 0; nt < 8; nt++)
#pragma unroll
        for (int r = 0; r < 4; r++) oacc[nt][r] = 0.f;
    float m0 = -INFINITY, m1 = -INFINITY, sl0 = 0.f, sl1 = 0.f;

    const float* penb = g_pen + (size_t)b * KLEN;
    const int T = KLEN / 64;
    attn_load_tile(sbase, 0, b, h, 0);
    cpa_commit();

    for (int kt = 0; kt < T; kt++) {
        if (kt + 1 < T) {
            attn_load_tile(sbase, (kt + 1) & 1, b, h, kt + 1);
            cpa_commit();
            cpa_wait<1>();
        } else {
            cpa_wait<0>();
        }
        __syncthreads();

        const uint32_t* Ks = smu + (kt & 1) * ABUFU;
        const uint32_t* Vs = smu + 2 * ABUFU + (kt & 1) * ABUFU;

        // ---- S = Q @ K^T (16 q-rows x 64 keys per warp)
        float sacc[8][4];
#pragma unroll
        for (int nt = 0; nt < 8; nt++)
#pragma unroll
            for (int r = 0; r < 4; r++) sacc[nt][r] = 0.f;

#pragma unroll
        for (int kk = 0; kk < 4; kk++) {
#pragma unroll
            for (int nt = 0; nt < 8; nt++) {
                int cb = kk * 16 + 2 * tk;
                uint2 b0 = *(const uint2*)&Ks[(nt * 8 + g) * RA + cb];
                uint2 b1 = *(const uint2*)&Ks[(nt * 8 + g) * RA + cb + 8];
                uint32_t bh[2] = {b0.x, b1.x};
                uint32_t bl[2] = {b0.y, b1.y};
                mma16(sacc[nt], qh[kk], bh);
                mma16(sacc[nt], ql[kk], bh);
                mma16(sacc[nt], qh[kk], bl);
            }
        }

        // ---- mask + online softmax (rows g, g+8)
        float mx0 = -INFINITY, mx1 = -INFINITY;
#pragma unroll
        for (int nt = 0; nt < 8; nt++) {
            float2 p2 = __ldg((const float2*)(penb + kt * 64 + nt * 8 + 2 * tk));
            sacc[nt][0] -= p2.x; sacc[nt][1] -= p2.y;
            sacc[nt][2] -= p2.x; sacc[nt][3] -= p2.y;
            mx0 = fmaxf(mx0, fmaxf(sacc[nt][0], sacc[nt][1]));
            mx1 = fmaxf(mx1, fmaxf(sacc[nt][2], sacc[nt][3]));
        }
        mx0 = fmaxf(mx0, __shfl_xor_sync(0xFFFFFFFFu, mx0, 1));
        mx0 = fmaxf(mx0, __shfl_xor_sync(0xFFFFFFFFu, mx0, 2));
        mx1 = fmaxf(mx1, __shfl_xor_sync(0xFFFFFFFFu, mx1, 1));
        mx1 = fmaxf(mx1, __shfl_xor_sync(0xFFFFFFFFu, mx1, 2));

        const float mn0 = fmaxf(m0, mx0), mn1 = fmaxf(m1, mx1);
        const float a0 = __expf(m0 - mn0), a1 = __expf(m1 - mn1);
        float ls0 = 0.f, ls1 = 0.f;
#pragma unroll
        for (int nt = 0; nt < 8; nt++) {
            sacc[nt][0] = __expf(sacc[nt][0] - mn0);
            sacc[nt][1] = __expf(sacc[nt][1] - mn0);
            sacc[nt][2] = __expf(sacc[nt][2] - mn1);
            sacc[nt][3] = __expf(sacc[nt][3] - mn1);
            ls0 += sacc[nt][0] + sacc[nt][1];
            ls1 += sacc[nt][2] + sacc[nt][3];
        }
        ls0 += __shfl_xor_sync(0xFFFFFFFFu, ls0, 1);
        ls0 += __shfl_xor_sync(0xFFFFFFFFu, ls0, 2);
        ls1 += __shfl_xor_sync(0xFFFFFFFFu, ls1, 1);
        ls1 += __shfl_xor_sync(0xFFFFFFFFu, ls1, 2);
        sl0 = sl0 * a0 + ls0;
        sl1 = sl1 * a1 + ls1;
        m0 = mn0; m1 = mn1;
#pragma unroll
        for (int nt = 0; nt < 8; nt++) {
            oacc[nt][0] *= a0; oacc[nt][1] *= a0;
            oacc[nt][2] *= a1; oacc[nt][3] *= a1;
        }

        // ---- PV: P fragments come straight from sacc (C layout == A layout)
#pragma unroll
        for (int kk = 0; kk < 4; kk++) {
            uint32_t ph[4], pl[4];
            packsplit(sacc[2 * kk][0],     sacc[2 * kk][1],     ph[0], pl[0]);
            packsplit(sacc[2 * kk][2],     sacc[2 * kk][3],     ph[1], pl[1]);
            packsplit(sacc[2 * kk + 1][0], sacc[2 * kk + 1][1], ph[2], pl[2]);
            packsplit(sacc[2 * kk + 1][2], sacc[2 * kk + 1][3], ph[3], pl[3]);
#pragma unroll
            for (int nt = 0; nt < 8; nt++) {
                int cb = kk * 16 + 2 * tk;
                uint2 v0 = *(const uint2*)&Vs[(nt * 8 + g) * RA + cb];
                uint2 v1 = *(const uint2*)&Vs[(nt * 8 + g) * RA + cb + 8];
                uint32_t vh[2] = {v0.x, v1.x};
                uint32_t vl[2] = {v0.y, v1.y};
                mma16(oacc[nt], ph, vh);
                mma16(oacc[nt], pl, vh);
                mma16(oacc[nt], ph, vl);
            }
        }
        __syncthreads();
    }

    // ---- epilogue: split-packed ctx for the output GEMM
    const float inv0 = 1.0f / sl0, inv1 = 1.0f / sl1;
    uint32_t* c0p = g_Cb + (size_t)(b * QLEN + q0 + wrow + g) * RU + h * HDIM;
    uint32_t* c1p = g_Cb + (size_t)(b * QLEN + q0 + wrow + g + 8) * RU + h * HDIM;
#pragma unroll
    for (int nt = 0; nt < 8; nt++) {
        int d = nt * 8 + 2 * tk;
        uint2 o;
        packsplit(oacc[nt][0] * inv0, oacc[nt][1] * inv0, o.x, o.y);
        *(uint2*)(c0p + d) = o;
        packsplit(oacc[nt][2] * inv1, oacc[nt][3] * inv1, o.x, o.y);
        *(uint2*)(c1p + d) = o;
    }
}

// ---------------------------------------------------------------------------
extern "C" void kernel_launch(void* const* d_in, const int* in_sizes, int n_in,
                              void* d_out, int out_size)
{
    (void)in_sizes; (void)n_in; (void)out_size;
    const float* query = (const float*)d_in[0];
    const float* key   = (const float*)d_in[1];
    const float* val   = (const float*)d_in[2];
    const int*   mask  = (const int*)  d_in[3];
    const float* Wq    = (const float*)d_in[4];
    const float* Wk    = (const float*)d_in[5];
    const float* Wv    = (const float*)d_in[6];
    const float* Wo    = (const float*)d_in[7];
    float* out = (float*)d_out;

    static int attrs_set = 0;
    if (!attrs_set) {
        cudaFuncSetAttribute(gemm_qkv,
                             cudaFuncAttributeMaxDynamicSharedMemorySize, GEMM_SMEM);
        cudaFuncSetAttribute(gemm_out,
                             cudaFuncAttributeMaxDynamicSharedMemorySize, GEMM_SMEM);
        cudaFuncSetAttribute(attn_tc,
                             cudaFuncAttributeMaxDynamicSharedMemorySize, ATT_SMEM);
        attrs_set = 1;
    }

    prep_split<<<2048, 256>>>(query, key, val, Wq, Wk, Wv, Wo, mask);

    dim3 gQKV(EMBED / 128, MROWS / 128, 3);     // (8, 32, 3)
    gemm_qkv<<<gQKV, 256, GEMM_SMEM>>>();

    dim3 gAttn(QLEN / 128, NHEAD, BATCH);       // (16, 16, 2)
    attn_tc<<<gAttn, 256, ATT_SMEM>>>();

    dim3 gOut(EMBED / 128, MROWS / 128);        // (8, 32)
    gemm_out<<<gOut, 256, GEMM_SMEM>>>(out);
}

// round 7
// speedup vs baseline: 3.8535x; 1.0260x over previous
#include <cuda_runtime.h>
#include <math.h>
#include <stdint.h>

#define EMBED 1024
#define NHEAD 16
#define HDIM  64
#define BATCH 2
#define QLEN  2048
#define KLEN  2048
#define MROWS (BATCH*QLEN)   // 4096
#define RU    1024           // u32 per packed row (1 u32 per element)

// ---------------------------------------------------------------------------
// Packed split-bf16: pair p = u32[2p]=bf16x2(hi x0,hi x1), u32[2p+1]=lo pair.
// ---------------------------------------------------------------------------
__device__ uint32_t g_in2[(size_t)3 * MROWS * RU];           // query2,key2,val2
__device__ uint32_t g_W2 [(size_t)4 * EMBED * RU];           // Wq2,Wk2,Wv2,Wo2
__device__ uint32_t g_Qb [(size_t)MROWS * RU];               // packed along d
__device__ uint32_t g_Kb [(size_t)MROWS * RU];               // packed along d
__device__ uint32_t g_Vb [(size_t)BATCH * NHEAD * HDIM * KLEN]; // [b][h][d][key-pairs]
__device__ uint32_t g_Cb [(size_t)MROWS * RU];               // ctx, packed along d
__device__ float    g_pen[(size_t)BATCH * KLEN];

// ---------------------------------------------------------------------------
// helpers
// ---------------------------------------------------------------------------
__device__ __forceinline__ void packsplit(float x0, float x1,
                                          uint32_t& hi, uint32_t& lo) {
    uint32_t h;
    asm("cvt.rn.bf16x2.f32 %0, %1, %2;" : "=r"(h) : "f"(x1), "f"(x0));
    float h0 = __uint_as_float(h << 16);
    float h1 = __uint_as_float(h & 0xffff0000u);
    float l0 = x0 - h0, l1 = x1 - h1;
    uint32_t l;
    asm("cvt.rn.bf16x2.f32 %0, %1, %2;" : "=r"(l) : "f"(l1), "f"(l0));
    hi = h; lo = l;
}

__device__ __forceinline__ void mma16(float* c, const uint32_t* a, const uint32_t* b) {
    asm volatile(
        "mma.sync.aligned.m16n8k16.row.col.f32.bf16.bf16.f32 "
        "{%0,%1,%2,%3}, {%4,%5,%6,%7}, {%8,%9}, {%0,%1,%2,%3};\n"
        : "+f"(c[0]), "+f"(c[1]), "+f"(c[2]), "+f"(c[3])
        : "r"(a[0]), "r"(a[1]), "r"(a[2]), "r"(a[3]), "r"(b[0]), "r"(b[1]));
}

__device__ __forceinline__ void cpa16(uint32_t dst, const void* src) {
    asm volatile("cp.async.cg.shared.global [%0], [%1], 16;\n" :: "r"(dst), "l"(src));
}
__device__ __forceinline__ void cpa_commit() {
    asm volatile("cp.async.commit_group;\n");
}
template <int N>
__device__ __forceinline__ void cpa_wait() {
    asm volatile("cp.async.wait_group %0;\n" :: "n"(N));
}

// ---------------------------------------------------------------------------
// prep: split inputs/weights into packed split-bf16; mask -> penalty floats.
// ---------------------------------------------------------------------------
#define SEG_IN  ((size_t)MROWS * EMBED / 4)
#define SEG_W   ((size_t)EMBED * EMBED / 4)
#define N_IN    (3 * SEG_IN)
#define N_W     (4 * SEG_W)
#define N_MASK  ((size_t)BATCH * KLEN / 4)

__global__ __launch_bounds__(256) void prep_split(
    const float* __restrict__ q,  const float* __restrict__ k,
    const float* __restrict__ v,
    const float* __restrict__ wq, const float* __restrict__ wk,
    const float* __restrict__ wv, const float* __restrict__ wo,
    const int* __restrict__ mask)
{
    const size_t total = N_IN + N_W + N_MASK;
    for (size_t u = (size_t)blockIdx.x * blockDim.x + threadIdx.x; u < total;
         u += (size_t)gridDim.x * blockDim.x) {
        if (u < N_IN) {
            int which = (int)(u / SEG_IN);
            size_t off = u - (size_t)which * SEG_IN;
            const float* src = which == 0 ? q : which == 1 ? k : v;
            float sc = which == 0 ? (1.0f / 32.0f) : 1.0f;
            float4 x = ((const float4*)src)[off];
            uint4 o;
            packsplit(x.x * sc, x.y * sc, o.x, o.y);
            packsplit(x.z * sc, x.w * sc, o.z, o.w);
            ((uint4*)(g_in2 + (size_t)which * MROWS * RU))[off] = o;
        } else if (u < N_IN + N_W) {
            size_t uu = u - N_IN;
            int which = (int)(uu / SEG_W);
            size_t off = uu - (size_t)which * SEG_W;
            const float* src = which == 0 ? wq : which == 1 ? wk
                              : which == 2 ? wv : wo;
            float4 x = ((const float4*)src)[off];
            uint4 o;
            packsplit(x.x, x.y, o.x, o.y);
            packsplit(x.z, x.w, o.z, o.w);
            ((uint4*)(g_W2 + (size_t)which * EMBED * RU))[off] = o;
        } else {
            size_t off = u - N_IN - N_W;
            int4 m = ((const int4*)mask)[off];
            float4 p;
            p.x = m.x ? 10000.0f : 0.0f;
            p.y = m.y ? 10000.0f : 0.0f;
            p.z = m.z ? 10000.0f : 0.0f;
            p.w = m.w ? 10000.0f : 0.0f;
            ((float4*)g_pen)[off] = p;
        }
    }
}

// ---------------------------------------------------------------------------
// GEMM core: 128x128 block tile, 128 thr = 4 warps (2m x 2n), warp 64x64.
// BK=32 elems, cp.async double buffer, smem row stride 40 u32.
// ---------------------------------------------------------------------------
#define RG 40
#define GBUFU (128 * RG)                       // 5120 u32 per buffer
#define GEMM_SMEM (4 * GBUFU * 4)              // 81920 B

__device__ __forceinline__ void gemm_load_tile(
    uint32_t sbase, int buf, const uint32_t* __restrict__ A2,
    const uint32_t* __restrict__ W2, int m0, int n0, int t)
{
    const int tid = threadIdx.x;
    const int kof = t * 32;
#pragma unroll
    for (int it = 0; it < 8; it++) {
        int l = tid + it * 128;
        int row = l >> 3, c = l & 7;
        cpa16(sbase + (uint32_t)((buf * GBUFU + row * RG + c * 4) * 4),
              A2 + (size_t)(m0 + row) * RU + kof + c * 4);
    }
#pragma unroll
    for (int it = 0; it < 8; it++) {
        int l = tid + it * 128;
        int row = l >> 3, c = l & 7;
        cpa16(sbase + (uint32_t)((2 * GBUFU + buf * GBUFU + row * RG + c * 4) * 4),
              W2 + (size_t)(n0 + row) * RU + kof + c * 4);
    }
}

__device__ __forceinline__ void gemm_core(
    const uint32_t* __restrict__ A2, const uint32_t* __restrict__ W2,
    uint32_t* smu, float acc[4][8][4], int m0, int n0)
{
    const int tid  = threadIdx.x;
    const int lane = tid & 31;
    const int w    = tid >> 5;
    const int g    = lane >> 2;
    const int tk   = lane & 3;
    const int wm   = (w & 1) * 64;
    const int wn   = (w >> 1) * 64;
    uint32_t sbase = (uint32_t)__cvta_generic_to_shared(smu);

#pragma unroll
    for (int mt = 0; mt < 4; mt++)
#pragma unroll
        for (int nt = 0; nt < 8; nt++)
#pragma unroll
            for (int r = 0; r < 4; r++) acc[mt][nt][r] = 0.f;

    const int T = EMBED / 32;   // 32 k-tiles
    gemm_load_tile(sbase, 0, A2, W2, m0, n0, 0);
    cpa_commit();

    for (int t = 0; t < T; t++) {
        if (t + 1 < T) {
            gemm_load_tile(sbase, (t + 1) & 1, A2, W2, m0, n0, t + 1);
            cpa_commit();
            cpa_wait<1>();
        } else {
            cpa_wait<0>();
        }
        __syncthreads();

        const uint32_t* As = smu + (t & 1) * GBUFU;
        const uint32_t* Bs = smu + 2 * GBUFU + (t & 1) * GBUFU;
#pragma unroll
        for (int kk = 0; kk < 2; kk++) {
            uint32_t ah[4][4], al[4][4];
            const int cb = kk * 16 + 2 * tk;
#pragma unroll
            for (int mt = 0; mt < 4; mt++) {
                int rb = wm + mt * 16;
                uint2 v;
                v = *(const uint2*)&As[(rb + g) * RG + cb];
                ah[mt][0] = v.x; al[mt][0] = v.y;
                v = *(const uint2*)&As[(rb + g + 8) * RG + cb];
                ah[mt][1] = v.x; al[mt][1] = v.y;
                v = *(const uint2*)&As[(rb + g) * RG + cb + 8];
                ah[mt][2] = v.x; al[mt][2] = v.y;
                v = *(const uint2*)&As[(rb + g + 8) * RG + cb + 8];
                ah[mt][3] = v.x; al[mt][3] = v.y;
            }
#pragma unroll
            for (int nt = 0; nt < 8; nt++) {
                uint2 b0 = *(const uint2*)&Bs[(wn + nt * 8 + g) * RG + cb];
                uint2 b1 = *(const uint2*)&Bs[(wn + nt * 8 + g) * RG + cb + 8];
                uint32_t bh[2] = {b0.x, b1.x};
                uint32_t bl[2] = {b0.y, b1.y};
#pragma unroll
                for (int mt = 0; mt < 4; mt++) {
                    mma16(acc[mt][nt], ah[mt], bh);
                    mma16(acc[mt][nt], al[mt], bh);
                    mma16(acc[mt][nt], ah[mt], bl);
                }
            }
        }
        __syncthreads();
    }
}

// QKV projections fused: z = 0 (Q), 1 (K), 2 (V, transposed split output).
__global__ __launch_bounds__(128, 2) void gemm_qkv()
{
    extern __shared__ uint32_t smu[];
    const int z = blockIdx.z;
    const uint32_t* A2 = g_in2 + (size_t)z * MROWS * RU;
    const uint32_t* W2 = g_W2 + (size_t)z * EMBED * RU;
    const int m0 = blockIdx.y * 128;
    const int n0 = blockIdx.x * 128;

    float acc[4][8][4];
    gemm_core(A2, W2, smu, acc, m0, n0);

    const int lane = threadIdx.x & 31;
    const int w    = threadIdx.x >> 5;
    const int g    = lane >> 2;
    const int tk   = lane & 3;
    const int wm   = (w & 1) * 64;
    const int wn   = (w >> 1) * 64;

    if (z < 2) {
        uint32_t* C2 = z == 0 ? g_Qb : g_Kb;
#pragma unroll
        for (int mt = 0; mt < 4; mt++) {
#pragma unroll
            for (int nt = 0; nt < 8; nt++) {
                int m = m0 + wm + mt * 16 + g;
                int n = n0 + wn + nt * 8 + 2 * tk;
                uint2 o;
                packsplit(acc[mt][nt][0], acc[mt][nt][1], o.x, o.y);
                *(uint2*)(C2 + (size_t)m * RU + n) = o;
                packsplit(acc[mt][nt][2], acc[mt][nt][3], o.x, o.y);
                *(uint2*)(C2 + (size_t)(m + 8) * RU + n) = o;
            }
        }
    } else {
        // V: write [b][h][d][key-pairs]; pair keys (g even, g odd) via shfl.
#pragma unroll
        for (int mt = 0; mt < 4; mt++) {
#pragma unroll
            for (int nt = 0; nt < 8; nt++) {
                float c0 = acc[mt][nt][0], c1 = acc[mt][nt][1];
                float c2 = acc[mt][nt][2], c3 = acc[mt][nt][3];
                float oc0 = __shfl_xor_sync(0xFFFFFFFFu, c0, 4);
                float oc1 = __shfl_xor_sync(0xFFFFFFFFu, c1, 4);
                float oc2 = __shfl_xor_sync(0xFFFFFFFFu, c2, 4);
                float oc3 = __shfl_xor_sync(0xFFFFFFFFu, c3, 4);
                if (!(g & 1)) {
                    int m = m0 + wm + mt * 16 + g;   // even key
                    int n = n0 + wn + nt * 8 + 2 * tk;
                    int b = m >> 11, key = m & 2047;
                    int hh = n >> 6, dl = n & 63;
                    uint32_t* base =
                        g_Vb + ((size_t)((b * NHEAD + hh) * HDIM + dl)) * KLEN;
                    uint2 o;
                    packsplit(c0, oc0, o.x, o.y);
                    *(uint2*)(base + key) = o;
                    packsplit(c2, oc2, o.x, o.y);
                    *(uint2*)(base + key + 8) = o;
                    packsplit(c1, oc1, o.x, o.y);
                    *(uint2*)(base + KLEN + key) = o;
                    packsplit(c3, oc3, o.x, o.y);
                    *(uint2*)(base + KLEN + key + 8) = o;
                }
            }
        }
    }
}

// Output projection: ctx2 @ Wo2^T -> plain fp32 out.
__global__ __launch_bounds__(128, 2) void gemm_out(float* __restrict__ out)
{
    extern __shared__ uint32_t smu[];
    const uint32_t* W2 = g_W2 + (size_t)3 * EMBED * RU;
    const int m0 = blockIdx.y * 128;
    const int n0 = blockIdx.x * 128;

    float acc[4][8][4];
    gemm_core(g_Cb, W2, smu, acc, m0, n0);

    const int lane = threadIdx.x & 31;
    const int w    = threadIdx.x >> 5;
    const int g    = lane >> 2;
    const int tk   = lane & 3;
    const int wm   = (w & 1) * 64;
    const int wn   = (w >> 1) * 64;
#pragma unroll
    for (int mt = 0; mt < 4; mt++) {
#pragma unroll
        for (int nt = 0; nt < 8; nt++) {
            int m = m0 + wm + mt * 16 + g;
            int n = n0 + wn + nt * 8 + 2 * tk;
            *(float2*)(out + (size_t)m * EMBED + n) =
                make_float2(acc[mt][nt][0], acc[mt][nt][1]);
            *(float2*)(out + (size_t)(m + 8) * EMBED + n) =
                make_float2(acc[mt][nt][2], acc[mt][nt][3]);
        }
    }
}

// ---------------------------------------------------------------------------
// Flash attention, split-bf16. Grid (QLEN/128, NHEAD, BATCH), 128 thr =
// 4 warps x 32 q-rows (2 m-tiles). K smem [key][d-pairs], V smem
// [d][key-pairs], stride 72 u32, cp.async double buffer.
// ---------------------------------------------------------------------------
#define RA 72
#define ABUFU (64 * RA)                        // 4608 u32
#define ATT_SMEM (4 * ABUFU * 4)               // 73728 B

__device__ __forceinline__ void attn_load_tile(uint32_t sbase, int buf,
                                               int b, int h, int kt)
{
    const int tid = threadIdx.x;
    const uint32_t* Kg = g_Kb + (size_t)(b * KLEN + kt * 64) * RU + h * HDIM;
    const uint32_t* Vg = g_Vb + ((size_t)(b * NHEAD + h) * HDIM) * KLEN + kt * 64;
#pragma unroll
    for (int it = 0; it < 8; it++) {
        int l = tid + it * 128;
        int row = l >> 4, c = l & 15;
        cpa16(sbase + (uint32_t)((buf * ABUFU + row * RA + c * 4) * 4),
              Kg + (size_t)row * RU + c * 4);
        cpa16(sbase + (uint32_t)((2 * ABUFU + buf * ABUFU + row * RA + c * 4) * 4),
              Vg + (size_t)row * KLEN + c * 4);
    }
}

__global__ __launch_bounds__(128, 2) void attn_tc()
{
    extern __shared__ uint32_t smu[];
    uint32_t sbase = (uint32_t)__cvta_generic_to_shared(smu);

    const int tid  = threadIdx.x;
    const int lane = tid & 31;
    const int w    = tid >> 5;
    const int g    = lane >> 2;
    const int tk   = lane & 3;
    const int qt = blockIdx.x, h = blockIdx.y, b = blockIdx.z;
    const int q0 = qt * 128;
    const int wrow = w * 32;

    // ---- Q fragments from packed gmem: 2 m-tiles x 4 k-tiles
    uint32_t qh[2][4][4], ql[2][4][4];
#pragma unroll
    for (int mt = 0; mt < 2; mt++) {
        const uint32_t* Qg =
            g_Qb + (size_t)(b * QLEN + q0 + wrow + mt * 16) * RU + h * HDIM;
#pragma unroll
        for (int kk = 0; kk < 4; kk++) {
            int cb = kk * 16 + 2 * tk;
            uint2 v;
            v = *(const uint2*)(Qg + (size_t)g * RU + cb);
            qh[mt][kk][0] = v.x; ql[mt][kk][0] = v.y;
            v = *(const uint2*)(Qg + (size_t)(g + 8) * RU + cb);
            qh[mt][kk][1] = v.x; ql[mt][kk][1] = v.y;
            v = *(const uint2*)(Qg + (size_t)g * RU + cb + 8);
            qh[mt][kk][2] = v.x; ql[mt][kk][2] = v.y;
            v = *(const uint2*)(Qg + (size_t)(g + 8) * RU + cb + 8);
            qh[mt][kk][3] = v.x; ql[mt][kk][3] = v.y;
        }
    }

    float oacc[2][8][4];
#pragma unroll
    for (int mt = 0; mt < 2; mt++)
#pragma unroll
        for (int nt = 0; nt < 8; nt++)
#pragma unroll
            for (int r = 0; r < 4; r++) oacc[mt][nt][r] = 0.f;
    float mrow[4] = {-INFINITY, -INFINITY, -INFINITY, -INFINITY};
    float lrow[4] = {0.f, 0.f, 0.f, 0.f};

    const float* penb = g_pen + (size_t)b * KLEN;
    const int T = KLEN / 64;
    attn_load_tile(sbase, 0, b, h, 0);
    cpa_commit();

    for (int kt = 0; kt < T; kt++) {
        if (kt + 1 < T) {
            attn_load_tile(sbase, (kt + 1) & 1, b, h, kt + 1);
            cpa_commit();
            cpa_wait<1>();
        } else {
            cpa_wait<0>();
        }
        __syncthreads();

        const uint32_t* Ks = smu + (kt & 1) * ABUFU;
        const uint32_t* Vs = smu + 2 * ABUFU + (kt & 1) * ABUFU;

        // ---- S = Q @ K^T (32 q-rows x 64 keys per warp)
        float sacc[2][8][4];
#pragma unroll
        for (int mt = 0; mt < 2; mt++)
#pragma unroll
            for (int nt = 0; nt < 8; nt++)
#pragma unroll
                for (int r = 0; r < 4; r++) sacc[mt][nt][r] = 0.f;

#pragma unroll
        for (int kk = 0; kk < 4; kk++) {
            const int cb = kk * 16 + 2 * tk;
#pragma unroll
            for (int nt = 0; nt < 8; nt++) {
                uint2 b0 = *(const uint2*)&Ks[(nt * 8 + g) * RA + cb];
                uint2 b1 = *(const uint2*)&Ks[(nt * 8 + g) * RA + cb + 8];
                uint32_t bh[2] = {b0.x, b1.x};
                uint32_t bl[2] = {b0.y, b1.y};
#pragma unroll
                for (int mt = 0; mt < 2; mt++) {
                    mma16(sacc[mt][nt], qh[mt][kk], bh);
                    mma16(sacc[mt][nt], ql[mt][kk], bh);
                    mma16(sacc[mt][nt], qh[mt][kk], bl);
                }
            }
        }

        // ---- mask + online softmax
        float2 p2[8];
#pragma unroll
        for (int nt = 0; nt < 8; nt++)
            p2[nt] = __ldg((const float2*)(penb + kt * 64 + nt * 8 + 2 * tk));

#pragma unroll
        for (int mt = 0; mt < 2; mt++) {
            float mx0 = -INFINITY, mx1 = -INFINITY;
#pragma unroll
            for (int nt = 0; nt < 8; nt++) {
                sacc[mt][nt][0] -= p2[nt].x; sacc[mt][nt][1] -= p2[nt].y;
                sacc[mt][nt][2] -= p2[nt].x; sacc[mt][nt][3] -= p2[nt].y;
                mx0 = fmaxf(mx0, fmaxf(sacc[mt][nt][0], sacc[mt][nt][1]));
                mx1 = fmaxf(mx1, fmaxf(sacc[mt][nt][2], sacc[mt][nt][3]));
            }
            mx0 = fmaxf(mx0, __shfl_xor_sync(0xFFFFFFFFu, mx0, 1));
            mx0 = fmaxf(mx0, __shfl_xor_sync(0xFFFFFFFFu, mx0, 2));
            mx1 = fmaxf(mx1, __shfl_xor_sync(0xFFFFFFFFu, mx1, 1));
            mx1 = fmaxf(mx1, __shfl_xor_sync(0xFFFFFFFFu, mx1, 2));

            const float mn0 = fmaxf(mrow[2 * mt], mx0);
            const float mn1 = fmaxf(mrow[2 * mt + 1], mx1);
            const float a0 = __expf(mrow[2 * mt] - mn0);
            const float a1 = __expf(mrow[2 * mt + 1] - mn1);
            float ls0 = 0.f, ls1 = 0.f;
#pragma unroll
            for (int nt = 0; nt < 8; nt++) {
                sacc[mt][nt][0] = __expf(sacc[mt][nt][0] - mn0);
                sacc[mt][nt][1] = __expf(sacc[mt][nt][1] - mn0);
                sacc[mt][nt][2] = __expf(sacc[mt][nt][2] - mn1);
                sacc[mt][nt][3] = __expf(sacc[mt][nt][3] - mn1);
                ls0 += sacc[mt][nt][0] + sacc[mt][nt][1];
                ls1 += sacc[mt][nt][2] + sacc[mt][nt][3];
            }
            ls0 += __shfl_xor_sync(0xFFFFFFFFu, ls0, 1);
            ls0 += __shfl_xor_sync(0xFFFFFFFFu, ls0, 2);
            ls1 += __shfl_xor_sync(0xFFFFFFFFu, ls1, 1);
            ls1 += __shfl_xor_sync(0xFFFFFFFFu, ls1, 2);
            lrow[2 * mt]     = lrow[2 * mt] * a0 + ls0;
            lrow[2 * mt + 1] = lrow[2 * mt + 1] * a1 + ls1;
            mrow[2 * mt] = mn0; mrow[2 * mt + 1] = mn1;
#pragma unroll
            for (int nt = 0; nt < 8; nt++) {
                oacc[mt][nt][0] *= a0; oacc[mt][nt][1] *= a0;
                oacc[mt][nt][2] *= a1; oacc[mt][nt][3] *= a1;
            }
        }

        // ---- PV: P fragments straight from sacc (C layout == A layout)
#pragma unroll
        for (int kk = 0; kk < 4; kk++) {
            uint32_t ph[2][4], pl[2][4];
#pragma unroll
            for (int mt = 0; mt < 2; mt++) {
                packsplit(sacc[mt][2 * kk][0],     sacc[mt][2 * kk][1],
                          ph[mt][0], pl[mt][0]);
                packsplit(sacc[mt][2 * kk][2],     sacc[mt][2 * kk][3],
                          ph[mt][1], pl[mt][1]);
                packsplit(sacc[mt][2 * kk + 1][0], sacc[mt][2 * kk + 1][1],
                          ph[mt][2], pl[mt][2]);
                packsplit(sacc[mt][2 * kk + 1][2], sacc[mt][2 * kk + 1][3],
                          ph[mt][3], pl[mt][3]);
            }
            const int cb = kk * 16 + 2 * tk;
#pragma unroll
            for (int nt = 0; nt < 8; nt++) {
                uint2 v0 = *(const uint2*)&Vs[(nt * 8 + g) * RA + cb];
                uint2 v1 = *(const uint2*)&Vs[(nt * 8 + g) * RA + cb + 8];
                uint32_t vh[2] = {v0.x, v1.x};
                uint32_t vl[2] = {v0.y, v1.y};
#pragma unroll
                for (int mt = 0; mt < 2; mt++) {
                    mma16(oacc[mt][nt], ph[mt], vh);
                    mma16(oacc[mt][nt], pl[mt], vh);
                    mma16(oacc[mt][nt], ph[mt], vl);
                }
            }
        }
        __syncthreads();
    }

    // ---- epilogue: split-packed ctx for the output GEMM
#pragma unroll
    for (int mt = 0; mt < 2; mt++) {
        const float inv0 = 1.0f / lrow[2 * mt];
        const float inv1 = 1.0f / lrow[2 * mt + 1];
        uint32_t* c0p = g_Cb +
            (size_t)(b * QLEN + q0 + wrow + mt * 16 + g) * RU + h * HDIM;
        uint32_t* c1p = g_Cb +
            (size_t)(b * QLEN + q0 + wrow + mt * 16 + g + 8) * RU + h * HDIM;
#pragma unroll
        for (int nt = 0; nt < 8; nt++) {
            int d = nt * 8 + 2 * tk;
            uint2 o;
            packsplit(oacc[mt][nt][0] * inv0, oacc[mt][nt][1] * inv0, o.x, o.y);
            *(uint2*)(c0p + d) = o;
            packsplit(oacc[mt][nt][2] * inv1, oacc[mt][nt][3] * inv1, o.x, o.y);
            *(uint2*)(c1p + d) = o;
        }
    }
}

// ---------------------------------------------------------------------------
extern "C" void kernel_launch(void* const* d_in, const int* in_sizes, int n_in,
                              void* d_out, int out_size)
{
    (void)in_sizes; (void)n_in; (void)out_size;
    const float* query = (const float*)d_in[0];
    const float* key   = (const float*)d_in[1];
    const float* val   = (const float*)d_in[2];
    const int*   mask  = (const int*)  d_in[3];
    const float* Wq    = (const float*)d_in[4];
    const float* Wk    = (const float*)d_in[5];
    const float* Wv    = (const float*)d_in[6];
    const float* Wo    = (const float*)d_in[7];
    float* out = (float*)d_out;

    static int attrs_set = 0;
    if (!attrs_set) {
        cudaFuncSetAttribute(gemm_qkv,
                             cudaFuncAttributeMaxDynamicSharedMemorySize, GEMM_SMEM);
        cudaFuncSetAttribute(gemm_out,
                             cudaFuncAttributeMaxDynamicSharedMemorySize, GEMM_SMEM);
        cudaFuncSetAttribute(attn_tc,
                             cudaFuncAttributeMaxDynamicSharedMemorySize, ATT_SMEM);
        attrs_set = 1;
    }

    prep_split<<<2048, 256>>>(query, key, val, Wq, Wk, Wv, Wo, mask);

    dim3 gQKV(EMBED / 128, MROWS / 128, 3);     // (8, 32, 3)
    gemm_qkv<<<gQKV, 128, GEMM_SMEM>>>();

    dim3 gAttn(QLEN / 128, NHEAD, BATCH);       // (16, 16, 2)
    attn_tc<<<gAttn, 128, ATT_SMEM>>>();

    dim3 gOut(EMBED / 128, MROWS / 128);        // (8, 32)
    gemm_out<<<gOut, 128, GEMM_SMEM>>>(out);
}

// round 9
// speedup vs baseline: 3.9471x; 1.0243x over previous
#include <cuda_runtime.h>
#include <math.h>
#include <stdint.h>

#define EMBED 1024
#define NHEAD 16
#define HDIM  64
#define BATCH 2
#define QLEN  2048
#define KLEN  2048
#define MROWS (BATCH*QLEN)   // 4096
#define RU    1024           // u32 per packed row (1 u32 per element)

// ---------------------------------------------------------------------------
// Packed split-bf16: pair p = u32[2p]=bf16x2(hi x0,hi x1), u32[2p+1]=lo pair.
// ---------------------------------------------------------------------------
__device__ uint32_t g_in2[(size_t)3 * MROWS * RU];           // query2,key2,val2
__device__ uint32_t g_W2 [(size_t)4 * EMBED * RU];           // Wq2,Wk2,Wv2,Wo2
__device__ uint32_t g_Qb [(size_t)MROWS * RU];               // packed along d
__device__ uint32_t g_Kb [(size_t)MROWS * RU];               // packed along d
__device__ uint32_t g_Vb [(size_t)BATCH * NHEAD * HDIM * KLEN]; // [b][h][d][key-pairs]
__device__ uint32_t g_Cb [(size_t)MROWS * RU];               // ctx, packed along d
__device__ float    g_pen[(size_t)BATCH * KLEN];

// ---------------------------------------------------------------------------
// helpers
// ---------------------------------------------------------------------------
__device__ __forceinline__ void packsplit(float x0, float x1,
                                          uint32_t& hi, uint32_t& lo) {
    uint32_t h;
    asm("cvt.rn.bf16x2.f32 %0, %1, %2;" : "=r"(h) : "f"(x1), "f"(x0));
    float h0 = __uint_as_float(h << 16);
    float h1 = __uint_as_float(h & 0xffff0000u);
    float l0 = x0 - h0, l1 = x1 - h1;
    uint32_t l;
    asm("cvt.rn.bf16x2.f32 %0, %1, %2;" : "=r"(l) : "f"(l1), "f"(l0));
    hi = h; lo = l;
}

__device__ __forceinline__ void mma16(float* c, const uint32_t* a, const uint32_t* b) {
    asm volatile(
        "mma.sync.aligned.m16n8k16.row.col.f32.bf16.bf16.f32 "
        "{%0,%1,%2,%3}, {%4,%5,%6,%7}, {%8,%9}, {%0,%1,%2,%3};\n"
        : "+f"(c[0]), "+f"(c[1]), "+f"(c[2]), "+f"(c[3])
        : "r"(a[0]), "r"(a[1]), "r"(a[2]), "r"(a[3]), "r"(b[0]), "r"(b[1]));
}

__device__ __forceinline__ void cpa16(uint32_t dst, const void* src) {
    asm volatile("cp.async.cg.shared.global [%0], [%1], 16;\n" :: "r"(dst), "l"(src));
}
__device__ __forceinline__ void cpa_commit() {
    asm volatile("cp.async.commit_group;\n");
}
template <int N>
__device__ __forceinline__ void cpa_wait() {
    asm volatile("cp.async.wait_group %0;\n" :: "n"(N));
}

// ---------------------------------------------------------------------------
// prep: split inputs/weights into packed split-bf16; mask -> penalty floats.
// ---------------------------------------------------------------------------
#define SEG_IN  ((size_t)MROWS * EMBED / 4)
#define SEG_W   ((size_t)EMBED * EMBED / 4)
#define N_IN    (3 * SEG_IN)
#define N_W     (4 * SEG_W)
#define N_MASK  ((size_t)BATCH * KLEN / 4)

__global__ __launch_bounds__(256) void prep_split(
    const float* __restrict__ q,  const float* __restrict__ k,
    const float* __restrict__ v,
    const float* __restrict__ wq, const float* __restrict__ wk,
    const float* __restrict__ wv, const float* __restrict__ wo,
    const int* __restrict__ mask)
{
    const size_t total = N_IN + N_W + N_MASK;
    for (size_t u = (size_t)blockIdx.x * blockDim.x + threadIdx.x; u < total;
         u += (size_t)gridDim.x * blockDim.x) {
        if (u < N_IN) {
            int which = (int)(u / SEG_IN);
            size_t off = u - (size_t)which * SEG_IN;
            const float* src = which == 0 ? q : which == 1 ? k : v;
            float sc = which == 0 ? (1.0f / 32.0f) : 1.0f;
            float4 x = ((const float4*)src)[off];
            uint4 o;
            packsplit(x.x * sc, x.y * sc, o.x, o.y);
            packsplit(x.z * sc, x.w * sc, o.z, o.w);
            ((uint4*)(g_in2 + (size_t)which * MROWS * RU))[off] = o;
        } else if (u < N_IN + N_W) {
            size_t uu = u - N_IN;
            int which = (int)(uu / SEG_W);
            size_t off = uu - (size_t)which * SEG_W;
            const float* src = which == 0 ? wq : which == 1 ? wk
                              : which == 2 ? wv : wo;
            float4 x = ((const float4*)src)[off];
            uint4 o;
            packsplit(x.x, x.y, o.x, o.y);
            packsplit(x.z, x.w, o.z, o.w);
            ((uint4*)(g_W2 + (size_t)which * EMBED * RU))[off] = o;
        } else {
            size_t off = u - N_IN - N_W;
            int4 m = ((const int4*)mask)[off];
            float4 p;
            p.x = m.x ? 10000.0f : 0.0f;
            p.y = m.y ? 10000.0f : 0.0f;
            p.z = m.z ? 10000.0f : 0.0f;
            p.w = m.w ? 10000.0f : 0.0f;
            ((float4*)g_pen)[off] = p;
        }
    }
}

// ---------------------------------------------------------------------------
// GEMM core: 128x128 block tile, 128 thr = 4 warps (2m x 2n), warp 64x64.
// BK=32 elems, cp.async double buffer, smem row stride 40 u32.
// Term-major MMA issue: all hh over (mt x 4nt), then lh, then hl.
// ---------------------------------------------------------------------------
#define RG 40
#define GBUFU (128 * RG)                       // 5120 u32 per buffer
#define GEMM_SMEM (4 * GBUFU * 4)              // 81920 B

__device__ __forceinline__ void gemm_load_tile(
    uint32_t sbase, int buf, const uint32_t* __restrict__ A2,
    const uint32_t* __restrict__ W2, int m0, int n0, int t)
{
    const int tid = threadIdx.x;
    const int kof = t * 32;
#pragma unroll
    for (int it = 0; it < 8; it++) {
        int l = tid + it * 128;
        int row = l >> 3, c = l & 7;
        cpa16(sbase + (uint32_t)((buf * GBUFU + row * RG + c * 4) * 4),
              A2 + (size_t)(m0 + row) * RU + kof + c * 4);
    }
#pragma unroll
    for (int it = 0; it < 8; it++) {
        int l = tid + it * 128;
        int row = l >> 3, c = l & 7;
        cpa16(sbase + (uint32_t)((2 * GBUFU + buf * GBUFU + row * RG + c * 4) * 4),
              W2 + (size_t)(n0 + row) * RU + kof + c * 4);
    }
}

__device__ __forceinline__ void gemm_core(
    const uint32_t* __restrict__ A2, const uint32_t* __restrict__ W2,
    uint32_t* smu, float acc[4][8][4], int m0, int n0)
{
    const int tid  = threadIdx.x;
    const int lane = tid & 31;
    const int w    = tid >> 5;
    const int g    = lane >> 2;
    const int tk   = lane & 3;
    const int wm   = (w & 1) * 64;
    const int wn   = (w >> 1) * 64;
    uint32_t sbase = (uint32_t)__cvta_generic_to_shared(smu);

#pragma unroll
    for (int mt = 0; mt < 4; mt++)
#pragma unroll
        for (int nt = 0; nt < 8; nt++)
#pragma unroll
            for (int r = 0; r < 4; r++) acc[mt][nt][r] = 0.f;

    const int T = EMBED / 32;   // 32 k-tiles
    gemm_load_tile(sbase, 0, A2, W2, m0, n0, 0);
    cpa_commit();

    for (int t = 0; t < T; t++) {
        if (t + 1 < T) {
            gemm_load_tile(sbase, (t + 1) & 1, A2, W2, m0, n0, t + 1);
            cpa_commit();
            cpa_wait<1>();
        } else {
            cpa_wait<0>();
        }
        __syncthreads();

        const uint32_t* As = smu + (t & 1) * GBUFU;
        const uint32_t* Bs = smu + 2 * GBUFU + (t & 1) * GBUFU;
#pragma unroll
        for (int kk = 0; kk < 2; kk++) {
            uint32_t ah[4][4], al[4][4];
            const int cb = kk * 16 + 2 * tk;
#pragma unroll
            for (int mt = 0; mt < 4; mt++) {
                int rb = wm + mt * 16;
                uint2 v;
                v = *(const uint2*)&As[(rb + g) * RG + cb];
                ah[mt][0] = v.x; al[mt][0] = v.y;
                v = *(const uint2*)&As[(rb + g + 8) * RG + cb];
                ah[mt][1] = v.x; al[mt][1] = v.y;
                v = *(const uint2*)&As[(rb + g) * RG + cb + 8];
                ah[mt][2] = v.x; al[mt][2] = v.y;
                v = *(const uint2*)&As[(rb + g + 8) * RG + cb + 8];
                ah[mt][3] = v.x; al[mt][3] = v.y;
            }
#pragma unroll
            for (int nh = 0; nh < 2; nh++) {
                uint32_t bh[4][2], bl[4][2];
#pragma unroll
                for (int j = 0; j < 4; j++) {
                    int nr = wn + (nh * 4 + j) * 8 + g;
                    uint2 b0 = *(const uint2*)&Bs[nr * RG + cb];
                    uint2 b1 = *(const uint2*)&Bs[nr * RG + cb + 8];
                    bh[j][0] = b0.x; bl[j][0] = b0.y;
                    bh[j][1] = b1.x; bl[j][1] = b1.y;
                }
                // term-major: 16 independent MMAs per term
#pragma unroll
                for (int j = 0; j < 4; j++)
#pragma unroll
                    for (int mt = 0; mt < 4; mt++)
                        mma16(acc[mt][nh * 4 + j], ah[mt], bh[j]);
#pragma unroll
                for (int j = 0; j < 4; j++)
#pragma unroll
                    for (int mt = 0; mt < 4; mt++)
                        mma16(acc[mt][nh * 4 + j], al[mt], bh[j]);
#pragma unroll
                for (int j = 0; j < 4; j++)
#pragma unroll
                    for (int mt = 0; mt < 4; mt++)
                        mma16(acc[mt][nh * 4 + j], ah[mt], bl[j]);
            }
        }
        __syncthreads();
    }
}

// QKV projections fused: z = 0 (Q), 1 (K), 2 (V, transposed split output).
__global__ __launch_bounds__(128, 2) void gemm_qkv()
{
    extern __shared__ uint32_t smu[];
    const int z = blockIdx.z;
    const uint32_t* A2 = g_in2 + (size_t)z * MROWS * RU;
    const uint32_t* W2 = g_W2 + (size_t)z * EMBED * RU;
    const int m0 = blockIdx.y * 128;
    const int n0 = blockIdx.x * 128;

    float acc[4][8][4];
    gemm_core(A2, W2, smu, acc, m0, n0);

    const int lane = threadIdx.x & 31;
    const int w    = threadIdx.x >> 5;
    const int g    = lane >> 2;
    const int tk   = lane & 3;
    const int wm   = (w & 1) * 64;
    const int wn   = (w >> 1) * 64;

    if (z < 2) {
        uint32_t* C2 = z == 0 ? g_Qb : g_Kb;
#pragma unroll
        for (int mt = 0; mt < 4; mt++) {
#pragma unroll
            for (int nt = 0; nt < 8; nt++) {
                int m = m0 + wm + mt * 16 + g;
                int n = n0 + wn + nt * 8 + 2 * tk;
                uint2 o;
                packsplit(acc[mt][nt][0], acc[mt][nt][1], o.x, o.y);
                *(uint2*)(C2 + (size_t)m * RU + n) = o;
                packsplit(acc[mt][nt][2], acc[mt][nt][3], o.x, o.y);
                *(uint2*)(C2 + (size_t)(m + 8) * RU + n) = o;
            }
        }
    } else {
        // V: write [b][h][d][key-pairs]; pair keys (g even, g odd) via shfl.
#pragma unroll
        for (int mt = 0; mt < 4; mt++) {
#pragma unroll
            for (int nt = 0; nt < 8; nt++) {
                float c0 = acc[mt][nt][0], c1 = acc[mt][nt][1];
                float c2 = acc[mt][nt][2], c3 = acc[mt][nt][3];
                float oc0 = __shfl_xor_sync(0xFFFFFFFFu, c0, 4);
                float oc1 = __shfl_xor_sync(0xFFFFFFFFu, c1, 4);
                float oc2 = __shfl_xor_sync(0xFFFFFFFFu, c2, 4);
                float oc3 = __shfl_xor_sync(0xFFFFFFFFu, c3, 4);
                if (!(g & 1)) {
                    int m = m0 + wm + mt * 16 + g;   // even key
                    int n = n0 + wn + nt * 8 + 2 * tk;
                    int b = m >> 11, key = m & 2047;
                    int hh = n >> 6, dl = n & 63;
                    uint32_t* base =
                        g_Vb + ((size_t)((b * NHEAD + hh) * HDIM + dl)) * KLEN;
                    uint2 o;
                    packsplit(c0, oc0, o.x, o.y);
                    *(uint2*)(base + key) = o;
                    packsplit(c2, oc2, o.x, o.y);
                    *(uint2*)(base + key + 8) = o;
                    packsplit(c1, oc1, o.x, o.y);
                    *(uint2*)(base + KLEN + key) = o;
                    packsplit(c3, oc3, o.x, o.y);
                    *(uint2*)(base + KLEN + key + 8) = o;
                }
            }
        }
    }
}

// Output projection: ctx2 @ Wo2^T -> plain fp32 out.
__global__ __launch_bounds__(128, 2) void gemm_out(float* __restrict__ out)
{
    extern __shared__ uint32_t smu[];
    const uint32_t* W2 = g_W2 + (size_t)3 * EMBED * RU;
    const int m0 = blockIdx.y * 128;
    const int n0 = blockIdx.x * 128;

    float acc[4][8][4];
    gemm_core(g_Cb, W2, smu, acc, m0, n0);

    const int lane = threadIdx.x & 31;
    const int w    = threadIdx.x >> 5;
    const int g    = lane >> 2;
    const int tk   = lane & 3;
    const int wm   = (w & 1) * 64;
    const int wn   = (w >> 1) * 64;
#pragma unroll
    for (int mt = 0; mt < 4; mt++) {
#pragma unroll
        for (int nt = 0; nt < 8; nt++) {
            int m = m0 + wm + mt * 16 + g;
            int n = n0 + wn + nt * 8 + 2 * tk;
            *(float2*)(out + (size_t)m * EMBED + n) =
                make_float2(acc[mt][nt][0], acc[mt][nt][1]);
            *(float2*)(out + (size_t)(m + 8) * EMBED + n) =
                make_float2(acc[mt][nt][2], acc[mt][nt][3]);
        }
    }
}

// ---------------------------------------------------------------------------
// Flash attention, split-bf16. Grid (QLEN/128, NHEAD, BATCH), 128 thr =
// 4 warps x 32 q-rows (2 m-tiles). Term-major MMA issue in S and PV phases.
// ---------------------------------------------------------------------------
#define RA 72
#define ABUFU (64 * RA)                        // 4608 u32
#define ATT_SMEM (4 * ABUFU * 4)               // 73728 B

__device__ __forceinline__ void attn_load_tile(uint32_t sbase, int buf,
                                               int b, int h, int kt)
{
    const int tid = threadIdx.x;
    const uint32_t* Kg = g_Kb + (size_t)(b * KLEN + kt * 64) * RU + h * HDIM;
    const uint32_t* Vg = g_Vb + ((size_t)(b * NHEAD + h) * HDIM) * KLEN + kt * 64;
#pragma unroll
    for (int it = 0; it < 8; it++) {
        int l = tid + it * 128;
        int row = l >> 4, c = l & 15;
        cpa16(sbase + (uint32_t)((buf * ABUFU + row * RA + c * 4) * 4),
              Kg + (size_t)row * RU + c * 4);
        cpa16(sbase + (uint32_t)((2 * ABUFU + buf * ABUFU + row * RA + c * 4) * 4),
              Vg + (size_t)row * KLEN + c * 4);
    }
}

__global__ __launch_bounds__(128, 2) void attn_tc()
{
    extern __shared__ uint32_t smu[];
    uint32_t sbase = (uint32_t)__cvta_generic_to_shared(smu);

    const int tid  = threadIdx.x;
    const int lane = tid & 31;
    const int w    = tid >> 5;
    const int g    = lane >> 2;
    const int tk   = lane & 3;
    const int qt = blockIdx.x, h = blockIdx.y, b = blockIdx.z;
    const int q0 = qt * 128;
    const int wrow = w * 32;

    // ---- Q fragments from packed gmem: 2 m-tiles x 4 k-tiles
    uint32_t qh[2][4][4], ql[2][4][4];
#pragma unroll
    for (int mt = 0; mt < 2; mt++) {
        const uint32_t* Qg =
            g_Qb + (size_t)(b * QLEN + q0 + wrow + mt * 16) * RU + h * HDIM;
#pragma unroll
        for (int kk = 0; kk < 4; kk++) {
            int cb = kk * 16 + 2 * tk;
            uint2 v;
            v = *(const uint2*)(Qg + (size_t)g * RU + cb);
            qh[mt][kk][0] = v.x; ql[mt][kk][0] = v.y;
            v = *(const uint2*)(Qg + (size_t)(g + 8) * RU + cb);
            qh[mt][kk][1] = v.x; ql[mt][kk][1] = v.y;
            v = *(const uint2*)(Qg + (size_t)g * RU + cb + 8);
            qh[mt][kk][2] = v.x; ql[mt][kk][2] = v.y;
            v = *(const uint2*)(Qg + (size_t)(g + 8) * RU + cb + 8);
            qh[mt][kk][3] = v.x; ql[mt][kk][3] = v.y;
        }
    }

    float oacc[2][8][4];
#pragma unroll
    for (int mt = 0; mt < 2; mt++)
#pragma unroll
        for (int nt = 0; nt < 8; nt++)
#pragma unroll
            for (int r = 0; r < 4; r++) oacc[mt][nt][r] = 0.f;
    float mrow[4] = {-INFINITY, -INFINITY, -INFINITY, -INFINITY};
    float lrow[4] = {0.f, 0.f, 0.f, 0.f};

    const float* penb = g_pen + (size_t)b * KLEN;
    const int T = KLEN / 64;
    attn_load_tile(sbase, 0, b, h, 0);
    cpa_commit();

    for (int kt = 0; kt < T; kt++) {
        if (kt + 1 < T) {
            attn_load_tile(sbase, (kt + 1) & 1, b, h, kt + 1);
            cpa_commit();
            cpa_wait<1>();
        } else {
            cpa_wait<0>();
        }
        __syncthreads();

        const uint32_t* Ks = smu + (kt & 1) * ABUFU;
        const uint32_t* Vs = smu + 2 * ABUFU + (kt & 1) * ABUFU;

        // ---- S = Q @ K^T (32 q-rows x 64 keys per warp), term-major
        float sacc[2][8][4];
#pragma unroll
        for (int mt = 0; mt < 2; mt++)
#pragma unroll
            for (int nt = 0; nt < 8; nt++)
#pragma unroll
                for (int r = 0; r < 4; r++) sacc[mt][nt][r] = 0.f;

#pragma unroll
        for (int kk = 0; kk < 4; kk++) {
            const int cb = kk * 16 + 2 * tk;
#pragma unroll
            for (int nh = 0; nh < 2; nh++) {
                uint32_t bh[4][2], bl[4][2];
#pragma unroll
                for (int j = 0; j < 4; j++) {
                    int nr = ((nh * 4 + j) * 8 + g) * RA + cb;
                    uint2 b0 = *(const uint2*)&Ks[nr];
                    uint2 b1 = *(const uint2*)&Ks[nr + 8];
                    bh[j][0] = b0.x; bl[j][0] = b0.y;
                    bh[j][1] = b1.x; bl[j][1] = b1.y;
                }
#pragma unroll
                for (int j = 0; j < 4; j++)
#pragma unroll
                    for (int mt = 0; mt < 2; mt++)
                        mma16(sacc[mt][nh * 4 + j], qh[mt][kk], bh[j]);
#pragma unroll
                for (int j = 0; j < 4; j++)
#pragma unroll
                    for (int mt = 0; mt < 2; mt++)
                        mma16(sacc[mt][nh * 4 + j], ql[mt][kk], bh[j]);
#pragma unroll
                for (int j = 0; j < 4; j++)
#pragma unroll
                    for (int mt = 0; mt < 2; mt++)
                        mma16(sacc[mt][nh * 4 + j], qh[mt][kk], bl[j]);
            }
        }

        // ---- mask + online softmax
        float2 p2[8];
#pragma unroll
        for (int nt = 0; nt < 8; nt++)
            p2[nt] = __ldg((const float2*)(penb + kt * 64 + nt * 8 + 2 * tk));

#pragma unroll
        for (int mt = 0; mt < 2; mt++) {
            float mx0 = -INFINITY, mx1 = -INFINITY;
#pragma unroll
            for (int nt = 0; nt < 8; nt++) {
                sacc[mt][nt][0] -= p2[nt].x; sacc[mt][nt][1] -= p2[nt].y;
                sacc[mt][nt][2] -= p2[nt].x; sacc[mt][nt][3] -= p2[nt].y;
                mx0 = fmaxf(mx0, fmaxf(sacc[mt][nt][0], sacc[mt][nt][1]));
                mx1 = fmaxf(mx1, fmaxf(sacc[mt][nt][2], sacc[mt][nt][3]));
            }
            mx0 = fmaxf(mx0, __shfl_xor_sync(0xFFFFFFFFu, mx0, 1));
            mx0 = fmaxf(mx0, __shfl_xor_sync(0xFFFFFFFFu, mx0, 2));
            mx1 = fmaxf(mx1, __shfl_xor_sync(0xFFFFFFFFu, mx1, 1));
            mx1 = fmaxf(mx1, __shfl_xor_sync(0xFFFFFFFFu, mx1, 2));

            const float mn0 = fmaxf(mrow[2 * mt], mx0);
            const float mn1 = fmaxf(mrow[2 * mt + 1], mx1);
            const float a0 = __expf(mrow[2 * mt] - mn0);
            const float a1 = __expf(mrow[2 * mt + 1] - mn1);
            float ls0 = 0.f, ls1 = 0.f;
#pragma unroll
            for (int nt = 0; nt < 8; nt++) {
                sacc[mt][nt][0] = __expf(sacc[mt][nt][0] - mn0);
                sacc[mt][nt][1] = __expf(sacc[mt][nt][1] - mn0);
                sacc[mt][nt][2] = __expf(sacc[mt][nt][2] - mn1);
                sacc[mt][nt][3] = __expf(sacc[mt][nt][3] - mn1);
                ls0 += sacc[mt][nt][0] + sacc[mt][nt][1];
                ls1 += sacc[mt][nt][2] + sacc[mt][nt][3];
            }
            ls0 += __shfl_xor_sync(0xFFFFFFFFu, ls0, 1);
            ls0 += __shfl_xor_sync(0xFFFFFFFFu, ls0, 2);
            ls1 += __shfl_xor_sync(0xFFFFFFFFu, ls1, 1);
            ls1 += __shfl_xor_sync(0xFFFFFFFFu, ls1, 2);
            lrow[2 * mt]     = lrow[2 * mt] * a0 + ls0;
            lrow[2 * mt + 1] = lrow[2 * mt + 1] * a1 + ls1;
            mrow[2 * mt] = mn0; mrow[2 * mt + 1] = mn1;
#pragma unroll
            for (int nt = 0; nt < 8; nt++) {
                oacc[mt][nt][0] *= a0; oacc[mt][nt][1] *= a0;
                oacc[mt][nt][2] *= a1; oacc[mt][nt][3] *= a1;
            }
        }

        // ---- PV: P fragments straight from sacc; term-major issue
#pragma unroll
        for (int kk = 0; kk < 4; kk++) {
            uint32_t ph[2][4], pl[2][4];
#pragma unroll
            for (int mt = 0; mt < 2; mt++) {
                packsplit(sacc[mt][2 * kk][0],     sacc[mt][2 * kk][1],
                          ph[mt][0], pl[mt][0]);
                packsplit(sacc[mt][2 * kk][2],     sacc[mt][2 * kk][3],
                          ph[mt][1], pl[mt][1]);
                packsplit(sacc[mt][2 * kk + 1][0], sacc[mt][2 * kk + 1][1],
                          ph[mt][2], pl[mt][2]);
                packsplit(sacc[mt][2 * kk + 1][2], sacc[mt][2 * kk + 1][3],
                          ph[mt][3], pl[mt][3]);
            }
            const int cb = kk * 16 + 2 * tk;
#pragma unroll
            for (int nh = 0; nh < 2; nh++) {
                uint32_t vh[4][2], vl[4][2];
#pragma unroll
                for (int j = 0; j < 4; j++) {
                    int nr = ((nh * 4 + j) * 8 + g) * RA + cb;
                    uint2 v0 = *(const uint2*)&Vs[nr];
                    uint2 v1 = *(const uint2*)&Vs[nr + 8];
                    vh[j][0] = v0.x; vl[j][0] = v0.y;
                    vh[j][1] = v1.x; vl[j][1] = v1.y;
                }
#pragma unroll
                for (int j = 0; j < 4; j++)
#pragma unroll
                    for (int mt = 0; mt < 2; mt++)
                        mma16(oacc[mt][nh * 4 + j], ph[mt], vh[j]);
#pragma unroll
                for (int j = 0; j < 4; j++)
#pragma unroll
                    for (int mt = 0; mt < 2; mt++)
                        mma16(oacc[mt][nh * 4 + j], pl[mt], vh[j]);
#pragma unroll
                for (int j = 0; j < 4; j++)
#pragma unroll
                    for (int mt = 0; mt < 2; mt++)
                        mma16(oacc[mt][nh * 4 + j], ph[mt], vl[j]);
            }
        }
        __syncthreads();
    }

    // ---- epilogue: split-packed ctx for the output GEMM
#pragma unroll
    for (int mt = 0; mt < 2; mt++) {
        const float inv0 = 1.0f / lrow[2 * mt];
        const float inv1 = 1.0f / lrow[2 * mt + 1];
        uint32_t* c0p = g_Cb +
            (size_t)(b * QLEN + q0 + wrow + mt * 16 + g) * RU + h * HDIM;
        uint32_t* c1p = g_Cb +
            (size_t)(b * QLEN + q0 + wrow + mt * 16 + g + 8) * RU + h * HDIM;
#pragma unroll
        for (int nt = 0; nt < 8; nt++) {
            int d = nt * 8 + 2 * tk;
            uint2 o;
            packsplit(oacc[mt][nt][0] * inv0, oacc[mt][nt][1] * inv0, o.x, o.y);
            *(uint2*)(c0p + d) = o;
            packsplit(oacc[mt][nt][2] * inv1, oacc[mt][nt][3] * inv1, o.x, o.y);
            *(uint2*)(c1p + d) = o;
        }
    }
}

// ---------------------------------------------------------------------------
extern "C" void kernel_launch(void* const* d_in, const int* in_sizes, int n_in,
                              void* d_out, int out_size)
{
    (void)in_sizes; (void)n_in; (void)out_size;
    const float* query = (const float*)d_in[0];
    const float* key   = (const float*)d_in[1];
    const float* val   = (const float*)d_in[2];
    const int*   mask  = (const int*)  d_in[3];
    const float* Wq    = (const float*)d_in[4];
    const float* Wk    = (const float*)d_in[5];
    const float* Wv    = (const float*)d_in[6];
    const float* Wo    = (const float*)d_in[7];
    float* out = (float*)d_out;

    static int attrs_set = 0;
    if (!attrs_set) {
        cudaFuncSetAttribute(gemm_qkv,
                             cudaFuncAttributeMaxDynamicSharedMemorySize, GEMM_SMEM);
        cudaFuncSetAttribute(gemm_out,
                             cudaFuncAttributeMaxDynamicSharedMemorySize, GEMM_SMEM);
        cudaFuncSetAttribute(attn_tc,
                             cudaFuncAttributeMaxDynamicSharedMemorySize, ATT_SMEM);
        attrs_set = 1;
    }

    prep_split<<<2048, 256>>>(query, key, val, Wq, Wk, Wv, Wo, mask);

    dim3 gQKV(EMBED / 128, MROWS / 128, 3);     // (8, 32, 3)
    gemm_qkv<<<gQKV, 128, GEMM_SMEM>>>();

    dim3 gAttn(QLEN / 128, NHEAD, BATCH);       // (16, 16, 2)
    attn_tc<<<gAttn, 128, ATT_SMEM>>>();

    dim3 gOut(EMBED / 128, MROWS / 128);        // (8, 32)
    gemm_out<<<gOut, 128, GEMM_SMEM>>>(out);
}